// round 13
// baseline (speedup 1.0000x reference)
#include <cuda_runtime.h>
#include <cuda_bf16.h>
#include <math.h>
#include <stdint.h>
#include <string.h>

#define NN 10000
#define EE 320000
#define ETOT (EE + NN)
#define IN_DIM 1280
#define HIDC 128
#define HEADS 4
#define HC 512
#define OUTD 500

#define WOFF1 0
#define WOFF2 (IN_DIM * HC)
#define WOFF3 (WOFF2 + HC * HC)
#define WTOT  (WOFF3 + HC * HC)

// ---------------- scratch (no allocations allowed) ----------------
__device__ float g_bufA[(size_t)NN * HC];
__device__ float g_bufB[(size_t)NN * HC];
__device__ __align__(16) unsigned short g_ah[(size_t)NN * IN_DIM];
__device__ __align__(16) unsigned short g_al[(size_t)NN * IN_DIM];
__device__ __align__(16) unsigned short g_wh[WTOT];
__device__ __align__(16) unsigned short g_wl[WTOT];
__device__ __align__(16) float g_s[NN * HEADS];
__device__ __align__(16) float g_dl[NN * HEADS];
__device__ int   g_deg[NN];          // zero at load; scan re-zeroes after use
__device__ int   g_rs[NN + 1];
__device__ int   g_cur[NN];
__device__ int   g_csrc[ETOT];
__device__ double g_sum[HC];
__device__ double g_sq[HC];
__device__ float g_scale[HC];
__device__ float g_shift[HC];

__device__ __forceinline__ unsigned short bf16bits(__nv_bfloat16 v) {
    unsigned short r;
    memcpy(&r, &v, 2);
    return r;
}

// ---------------- CSR build ----------------
__global__ void hist_kernel(const int* __restrict__ ei) {
    int e = blockIdx.x * blockDim.x + threadIdx.x;
    if (e < ETOT) {
        int dst = (e < EE) ? ei[EE + e] : (e - EE);
        atomicAdd(&g_deg[dst], 1);
    }
}

__global__ void scan_kernel() {
    __shared__ int sm[1024];
    int tid = threadIdx.x;
    const int per = (NN + 1023) / 1024;
    int b = tid * per;
    int e = min(b + per, NN);
    int local = 0;
    for (int i = b; i < e; i++) local += g_deg[i];
    sm[tid] = local;
    __syncthreads();
    for (int off = 1; off < 1024; off <<= 1) {
        int v = (tid >= off) ? sm[tid - off] : 0;
        __syncthreads();
        sm[tid] += v;
        __syncthreads();
    }
    int run = sm[tid] - local;
    for (int i = b; i < e; i++) {
        g_rs[i] = run;
        g_cur[i] = run;
        run += g_deg[i];
    }
    // re-zero for next call (each entry owned by exactly this thread)
    for (int i = b; i < e; i++) g_deg[i] = 0;
    if (tid == 1023) g_rs[NN] = run;
}

__global__ void scatter_kernel(const int* __restrict__ ei) {
    int e = blockIdx.x * blockDim.x + threadIdx.x;
    if (e < ETOT) {
        int src, dst;
        if (e < EE) { src = ei[e]; dst = ei[EE + e]; }
        else        { src = dst = e - EE; }
        int p = atomicAdd(&g_cur[dst], 1);
        g_csrc[p] = src;
    }
}

// ---------------- bf16 H/L pre-split ----------------
__global__ void splita_kernel(const float* __restrict__ x,
                              unsigned short* __restrict__ h,
                              unsigned short* __restrict__ l, int n4) {
    int i = blockIdx.x * blockDim.x + threadIdx.x;
    if (i < n4) {
        float4 v = reinterpret_cast<const float4*>(x)[i];
        __nv_bfloat16 hx = __float2bfloat16_rn(v.x);
        __nv_bfloat16 hy = __float2bfloat16_rn(v.y);
        __nv_bfloat16 hz = __float2bfloat16_rn(v.z);
        __nv_bfloat16 hw = __float2bfloat16_rn(v.w);
        ushort4 H, L;
        H.x = bf16bits(hx); H.y = bf16bits(hy); H.z = bf16bits(hz); H.w = bf16bits(hw);
        L.x = bf16bits(__float2bfloat16_rn(v.x - __bfloat162float(hx)));
        L.y = bf16bits(__float2bfloat16_rn(v.y - __bfloat162float(hy)));
        L.z = bf16bits(__float2bfloat16_rn(v.z - __bfloat162float(hz)));
        L.w = bf16bits(__float2bfloat16_rn(v.w - __bfloat162float(hw)));
        reinterpret_cast<ushort4*>(h)[i] = H;
        reinterpret_cast<ushort4*>(l)[i] = L;
    }
}

// weight split w/ optional column pad + optional s/d zeroing (layer 3)
__global__ void splitw_kernel(const float* __restrict__ B,
                              unsigned short* __restrict__ h,
                              unsigned short* __restrict__ l,
                              int K, int Ns, int Nd, int woff, int zsd) {
    int i = blockIdx.x * blockDim.x + threadIdx.x;
    if (zsd && i < NN * HEADS) { g_s[i] = 0.f; g_dl[i] = 0.f; }
    if (i < K * Nd) {
        int r = i / Nd, c = i - r * Nd;
        float v = (c < Ns) ? B[r * Ns + c] : 0.f;
        __nv_bfloat16 hh = __float2bfloat16_rn(v);
        h[woff + i] = bf16bits(hh);
        l[woff + i] = bf16bits(__float2bfloat16_rn(v - __bfloat162float(hh)));
    }
}

// =====================================================================
//  cp.async + ldmatrix bf16x3 GEMM, 64M x 128N tile, 3 CTAs/SM,
//  single barrier per k-tile; fused s/d epilogue.
// =====================================================================
__device__ __forceinline__ void mma_bf16(float* c, const uint32_t* a, const uint32_t* b) {
    asm volatile(
        "mma.sync.aligned.m16n8k16.row.col.f32.bf16.bf16.f32 "
        "{%0,%1,%2,%3}, {%4,%5,%6,%7}, {%8,%9}, {%0,%1,%2,%3};\n"
        : "+f"(c[0]), "+f"(c[1]), "+f"(c[2]), "+f"(c[3])
        : "r"(a[0]), "r"(a[1]), "r"(a[2]), "r"(a[3]), "r"(b[0]), "r"(b[1]));
}

__device__ __forceinline__ void ldsm4(uint32_t* r, uint32_t a) {
    asm volatile("ldmatrix.sync.aligned.m8n8.x4.shared.b16 {%0,%1,%2,%3},[%4];"
                 : "=r"(r[0]), "=r"(r[1]), "=r"(r[2]), "=r"(r[3]) : "r"(a));
}
__device__ __forceinline__ void ldsm4t(uint32_t* r, uint32_t a) {
    asm volatile("ldmatrix.sync.aligned.m8n8.x4.trans.shared.b16 {%0,%1,%2,%3},[%4];"
                 : "=r"(r[0]), "=r"(r[1]), "=r"(r[2]), "=r"(r[3]) : "r"(a));
}
__device__ __forceinline__ void cpa16(uint32_t s, const void* g, int vbytes) {
    asm volatile("cp.async.cg.shared.global [%0],[%1],16,%2;" :: "r"(s), "l"(g), "r"(vbytes));
}

#define GEMM_STAGE 27648
#define SMEM_GEMM_BYTES (2 * GEMM_STAGE)

__global__ __launch_bounds__(256, 3) void gemm_cp(int M, int N, int Nb, int K,
        const unsigned short* __restrict__ Ah, const unsigned short* __restrict__ Al,
        const unsigned short* __restrict__ Bh, const unsigned short* __restrict__ Bl,
        float* __restrict__ C,
        const float* __restrict__ asrc, const float* __restrict__ adst,
        int Hh, int Cc) {
    extern __shared__ __align__(16) unsigned char smp[];
    uint32_t sb = (uint32_t)__cvta_generic_to_shared(smp);

    const int tid = threadIdx.x;
    const int lane = tid & 31;
    const int warp = tid >> 5;
    const int g = lane >> 2;
    const int tq = lane & 3;
    const int warpM = warp & 1;
    const int warpN = warp >> 1;
    const int rowBase = blockIdx.y * 64;
    const int colBase = blockIdx.x * 128;
    const int numKT = K / 32;

    auto issueLoads = [&](int kt, int s) {
        uint32_t st = sb + s * GEMM_STAGE;
        {
            int row = tid >> 2, ch = tid & 3;
            int gr = rowBase + row;
            int v = (gr < M) ? 16 : 0;
            size_t goff = (size_t)((gr < M) ? gr : 0) * K + kt * 32 + ch * 8;
            uint32_t d = row * 80 + ch * 16;
            cpa16(st + d, Ah + goff, v);
            cpa16(st + 5120 + d, Al + goff, v);
        }
#pragma unroll
        for (int i = 0; i < 2; i++) {
            int idx = tid + i * 256;
            int row = idx >> 4, ch = idx & 15;
            size_t goff = (size_t)(kt * 32 + row) * Nb + colBase + ch * 8;
            uint32_t d = row * 272 + ch * 16;
            cpa16(st + 10240 + d, Bh + goff, 16);
            cpa16(st + 18944 + d, Bl + goff, 16);
        }
        asm volatile("cp.async.commit_group;");
    };

    float acc[2][4][4];
#pragma unroll
    for (int mt = 0; mt < 2; mt++)
#pragma unroll
        for (int nt = 0; nt < 4; nt++)
#pragma unroll
            for (int q = 0; q < 4; q++) acc[mt][nt][q] = 0.f;

    issueLoads(0, 0);

    for (int kt = 0; kt < numKT; kt++) {
        asm volatile("cp.async.wait_group 0;");
        __syncthreads();      // single barrier per k-tile:
                              // all own-copies done before it -> all tiles visible;
                              // all warps past previous compute (other buffer) -> safe to overwrite
        int cur = kt & 1;
        if (kt + 1 < numKT) issueLoads(kt + 1, cur ^ 1);

        uint32_t st = sb + cur * GEMM_STAGE;

#pragma unroll
        for (int ks = 0; ks < 2; ks++) {
            uint32_t aH[2][4], aL[2][4];
#pragma unroll
            for (int mt = 0; mt < 2; mt++) {
                uint32_t off = (uint32_t)(warpM * 32 + mt * 16 + (lane & 15)) * 80
                             + (ks * 16 + (lane >> 4) * 8) * 2;
                ldsm4(aH[mt], st + off);
                ldsm4(aL[mt], st + 5120 + off);
            }
#pragma unroll
            for (int ntp = 0; ntp < 2; ntp++) {
                uint32_t boff = (uint32_t)(ks * 16 + (lane & 15)) * 272
                              + (warpN * 32 + ntp * 16 + (lane >> 4) * 8) * 2;
                uint32_t bh[4], bl[4];
                ldsm4t(bh, st + 10240 + boff);
                ldsm4t(bl, st + 18944 + boff);
#pragma unroll
                for (int mt = 0; mt < 2; mt++) {
                    mma_bf16(acc[mt][ntp * 2 + 0], aH[mt], bh + 0);
                    mma_bf16(acc[mt][ntp * 2 + 1], aH[mt], bh + 2);
                    mma_bf16(acc[mt][ntp * 2 + 0], aL[mt], bh + 0);
                    mma_bf16(acc[mt][ntp * 2 + 1], aL[mt], bh + 2);
                    mma_bf16(acc[mt][ntp * 2 + 0], aH[mt], bl + 0);
                    mma_bf16(acc[mt][ntp * 2 + 1], aH[mt], bl + 2);
                }
            }
        }
        // no trailing barrier: next iteration's (wait, sync) provides ordering
    }
    __syncthreads();   // protect smem reuse in epilogue below

    // ---- store C ----
#pragma unroll
    for (int mt = 0; mt < 2; mt++) {
        int r0 = rowBase + warpM * 32 + mt * 16 + g;
        int r1 = r0 + 8;
#pragma unroll
        for (int nt = 0; nt < 4; nt++) {
            int c0 = colBase + warpN * 32 + nt * 8 + tq * 2;
            if (r0 < M) {
                if (c0 < N)     C[(size_t)r0 * N + c0]     = acc[mt][nt][0];
                if (c0 + 1 < N) C[(size_t)r0 * N + c0 + 1] = acc[mt][nt][1];
            }
            if (r1 < M) {
                if (c0 < N)     C[(size_t)r1 * N + c0]     = acc[mt][nt][2];
                if (c0 + 1 < N) C[(size_t)r1 * N + c0 + 1] = acc[mt][nt][3];
            }
        }
    }

    // ---- fused s/d epilogue (CTA-local reduction) ----
    {
        float sp[2][2] = {{0.f, 0.f}, {0.f, 0.f}};
        float dp[2][2] = {{0.f, 0.f}, {0.f, 0.f}};
#pragma unroll
        for (int nt = 0; nt < 4; nt++) {
            int c0 = colBase + warpN * 32 + nt * 8 + tq * 2;
            if (c0 < N) {
                float a0 = asrc[c0];
                float d0 = adst[c0];
                float a1 = (c0 + 1 < N) ? asrc[c0 + 1] : 0.f;
                float d1 = (c0 + 1 < N) ? adst[c0 + 1] : 0.f;
#pragma unroll
                for (int mt = 0; mt < 2; mt++) {
                    sp[mt][0] += acc[mt][nt][0] * a0 + acc[mt][nt][1] * a1;
                    sp[mt][1] += acc[mt][nt][2] * a0 + acc[mt][nt][3] * a1;
                    dp[mt][0] += acc[mt][nt][0] * d0 + acc[mt][nt][1] * d1;
                    dp[mt][1] += acc[mt][nt][2] * d0 + acc[mt][nt][3] * d1;
                }
            }
        }
#pragma unroll
        for (int off = 1; off <= 2; off <<= 1) {
#pragma unroll
            for (int mt = 0; mt < 2; mt++)
#pragma unroll
                for (int rr = 0; rr < 2; rr++) {
                    sp[mt][rr] += __shfl_xor_sync(0xFFFFFFFF, sp[mt][rr], off);
                    dp[mt][rr] += __shfl_xor_sync(0xFFFFFFFF, dp[mt][rr], off);
                }
        }
        float* sredS = (float*)smp;          // [64][4]
        float* sredD = (float*)smp + 256;    // [64][4]
        if (tq == 0) {
#pragma unroll
            for (int mt = 0; mt < 2; mt++)
#pragma unroll
                for (int rr = 0; rr < 2; rr++) {
                    int rl = warpM * 32 + mt * 16 + rr * 8 + g;
                    sredS[rl * 4 + warpN] = sp[mt][rr];
                    sredD[rl * 4 + warpN] = dp[mt][rr];
                }
        }
        __syncthreads();
        if (tid < 64) {
            int r = rowBase + tid;
            if (r < M) {
                float ss = sredS[tid * 4] + sredS[tid * 4 + 1]
                         + sredS[tid * 4 + 2] + sredS[tid * 4 + 3];
                float dd = sredD[tid * 4] + sredD[tid * 4 + 1]
                         + sredD[tid * 4 + 2] + sredD[tid * 4 + 3];
                if (Cc == 128) {
                    g_s[r * Hh + blockIdx.x] = ss;
                    g_dl[r * Hh + blockIdx.x] = dd;
                } else {
                    atomicAdd(&g_s[r], ss);
                    atomicAdd(&g_dl[r], dd);
                }
            }
        }
    }
}

// ---------------- fused softmax + weighted gather per dst node ----------------
template <int H, int C>
__global__ __launch_bounds__(128) void gather_fused(const float* __restrict__ xp,
                                                    const float* __restrict__ bias,
                                                    float* __restrict__ out,
                                                    int bnzero) {
    constexpr int HCc = H * C;
    const int v = blockIdx.x;
    const int tid = threadIdx.x;
    const int lane = tid & 31;
    const int wid = tid >> 5;
    const int start = g_rs[v], end = g_rs[v + 1];
    const int deg = end - start;

    if (bnzero && v == 0) {
        for (int i = tid; i < HC; i += 128) { g_sum[i] = 0.0; g_sq[i] = 0.0; }
    }

    __shared__ float wsh[128 * H];
    __shared__ int ssh[128];
    __shared__ float red[4 * H];
    __shared__ float zish[H];

    float dv[H];
    if (H == 4) {
        float4 t = *reinterpret_cast<const float4*>(&g_dl[v * 4]);
        dv[0] = t.x; dv[1] = t.y; dv[2] = t.z; dv[3] = t.w;
    } else {
        dv[0] = g_dl[v];
    }

    const int c0 = tid * 4;
    const bool active = c0 < HCc;
    const int hh = active ? (c0 / C) : 0;
    float4 acc = make_float4(0.f, 0.f, 0.f, 0.f);

    auto gatherBatch = [&](int cnt, float zmul) {
        if (active) {
            int j = 0;
            // 16 independent loads in flight
            for (; j + 16 <= cnt; j += 16) {
                float w[16];
                float4 xv[16];
#pragma unroll
                for (int q = 0; q < 16; q++) {
                    w[q] = wsh[(j + q) * H + hh] * zmul;
                    xv[q] = *reinterpret_cast<const float4*>(
                        xp + (size_t)ssh[j + q] * HCc + c0);
                }
#pragma unroll
                for (int q = 0; q < 16; q++) {
                    acc.x += w[q] * xv[q].x;
                    acc.y += w[q] * xv[q].y;
                    acc.z += w[q] * xv[q].z;
                    acc.w += w[q] * xv[q].w;
                }
            }
            for (; j + 8 <= cnt; j += 8) {
                float w[8];
                float4 xv[8];
#pragma unroll
                for (int q = 0; q < 8; q++) {
                    w[q] = wsh[(j + q) * H + hh] * zmul;
                    xv[q] = *reinterpret_cast<const float4*>(
                        xp + (size_t)ssh[j + q] * HCc + c0);
                }
#pragma unroll
                for (int q = 0; q < 8; q++) {
                    acc.x += w[q] * xv[q].x;
                    acc.y += w[q] * xv[q].y;
                    acc.z += w[q] * xv[q].z;
                    acc.w += w[q] * xv[q].w;
                }
            }
            for (; j < cnt; j++) {
                float w = wsh[j * H + hh] * zmul;
                const float4 xv = *reinterpret_cast<const float4*>(
                    xp + (size_t)ssh[j] * HCc + c0);
                acc.x += w * xv.x;
                acc.y += w * xv.y;
                acc.z += w * xv.z;
                acc.w += w * xv.w;
            }
        }
    };

    if (deg <= 128) {
        float ex[H];
#pragma unroll
        for (int h = 0; h < H; h++) ex[h] = 0.f;
        if (tid < deg) {
            int se = g_csrc[start + tid];
            ssh[tid] = se;
            float sv[H];
            if (H == 4) {
                float4 t = *reinterpret_cast<const float4*>(&g_s[se * 4]);
                sv[0] = t.x; sv[1] = t.y; sv[2] = t.z; sv[3] = t.w;
            } else {
                sv[0] = g_s[se];
            }
#pragma unroll
            for (int h = 0; h < H; h++) {
                float l = sv[h] + dv[h];
                l = l > 0.f ? l : 0.2f * l;
                ex[h] = __expf(l);
                wsh[tid * H + h] = ex[h];
            }
        }
#pragma unroll
        for (int h = 0; h < H; h++)
#pragma unroll
            for (int off = 16; off > 0; off >>= 1)
                ex[h] += __shfl_xor_sync(0xFFFFFFFF, ex[h], off);
        if (lane == 0) {
#pragma unroll
            for (int h = 0; h < H; h++) red[wid * H + h] = ex[h];
        }
        __syncthreads();
        if (tid < H)
            zish[tid] = 1.f / (red[tid] + red[H + tid] + red[2 * H + tid] + red[3 * H + tid]);
        __syncthreads();
        float zmul = zish[hh];
        gatherBatch(deg, zmul);
    } else {
        float lsum[H];
#pragma unroll
        for (int h = 0; h < H; h++) lsum[h] = 0.f;
        for (int e = start + tid; e < end; e += 128) {
            int se = g_csrc[e];
            float sv[H];
            if (H == 4) {
                float4 t = *reinterpret_cast<const float4*>(&g_s[se * 4]);
                sv[0] = t.x; sv[1] = t.y; sv[2] = t.z; sv[3] = t.w;
            } else {
                sv[0] = g_s[se];
            }
#pragma unroll
            for (int h = 0; h < H; h++) {
                float l = sv[h] + dv[h];
                l = l > 0.f ? l : 0.2f * l;
                lsum[h] += __expf(l);
            }
        }
#pragma unroll
        for (int h = 0; h < H; h++)
#pragma unroll
            for (int off = 16; off > 0; off >>= 1)
                lsum[h] += __shfl_xor_sync(0xFFFFFFFF, lsum[h], off);
        if (lane == 0) {
#pragma unroll
            for (int h = 0; h < H; h++) red[wid * H + h] = lsum[h];
        }
        __syncthreads();
        if (tid < H)
            zish[tid] = 1.f / (red[tid] + red[H + tid] + red[2 * H + tid] + red[3 * H + tid]);
        __syncthreads();
        float zmul = zish[hh];

        for (int base = start; base < end; base += 128) {
            int cnt = min(128, end - base);
            __syncthreads();
            if (tid < cnt) {
                int se = g_csrc[base + tid];
                ssh[tid] = se;
                float sv[H];
                if (H == 4) {
                    float4 t = *reinterpret_cast<const float4*>(&g_s[se * 4]);
                    sv[0] = t.x; sv[1] = t.y; sv[2] = t.z; sv[3] = t.w;
                } else {
                    sv[0] = g_s[se];
                }
#pragma unroll
                for (int h = 0; h < H; h++) {
                    float l = sv[h] + dv[h];
                    l = l > 0.f ? l : 0.2f * l;
                    wsh[tid * H + h] = __expf(l);
                }
            }
            __syncthreads();
            gatherBatch(cnt, zmul);
        }
    }

    if (active) {
        const float4 bb = *reinterpret_cast<const float4*>(bias + c0);
        float* o = out + (size_t)v * HCc + c0;
        o[0] = acc.x + bb.x;
        o[1] = acc.y + bb.y;
        o[2] = acc.z + bb.z;
        o[3] = acc.w + bb.w;
    }
}

// ---------------- BatchNorm (+ELU) ----------------
__global__ void bn_stats_kernel(const float* __restrict__ x) {
    int c = threadIdx.x;
    int r0 = blockIdx.x * 256;
    int r1 = min(r0 + 256, NN);
    double s = 0.0, q = 0.0;
    for (int r = r0; r < r1; r++) {
        float v = x[(size_t)r * HC + c];
        s += v;
        q += (double)v * (double)v;
    }
    atomicAdd(&g_sum[c], s);
    atomicAdd(&g_sq[c], q);
}

__global__ void bn_final_kernel(const float* __restrict__ gam,
                                const float* __restrict__ bet) {
    int c = threadIdx.x;
    if (c < HC) {
        double mu = g_sum[c] / NN;
        double var = g_sq[c] / NN - mu * mu;
        float sc = rsqrtf((float)var + 1e-5f) * gam[c];
        g_scale[c] = sc;
        g_shift[c] = bet[c] - (float)mu * sc;
    }
}

__global__ void bn_apply_split_kernel(const float* __restrict__ x,
                                      unsigned short* __restrict__ h,
                                      unsigned short* __restrict__ l) {
    int i = blockIdx.x * blockDim.x + threadIdx.x;
    const int n4 = NN * HC / 4;
    if (i < n4) {
        float4 v = reinterpret_cast<const float4*>(x)[i];
        int c0 = (i * 4) & (HC - 1);
        float y0 = v.x * g_scale[c0 + 0] + g_shift[c0 + 0];
        float y1 = v.y * g_scale[c0 + 1] + g_shift[c0 + 1];
        float y2 = v.z * g_scale[c0 + 2] + g_shift[c0 + 2];
        float y3 = v.w * g_scale[c0 + 3] + g_shift[c0 + 3];
        y0 = y0 > 0.f ? y0 : expm1f(y0);
        y1 = y1 > 0.f ? y1 : expm1f(y1);
        y2 = y2 > 0.f ? y2 : expm1f(y2);
        y3 = y3 > 0.f ? y3 : expm1f(y3);
        __nv_bfloat16 h0 = __float2bfloat16_rn(y0);
        __nv_bfloat16 h1 = __float2bfloat16_rn(y1);
        __nv_bfloat16 h2 = __float2bfloat16_rn(y2);
        __nv_bfloat16 h3 = __float2bfloat16_rn(y3);
        ushort4 H, L;
        H.x = bf16bits(h0); H.y = bf16bits(h1); H.z = bf16bits(h2); H.w = bf16bits(h3);
        L.x = bf16bits(__float2bfloat16_rn(y0 - __bfloat162float(h0)));
        L.y = bf16bits(__float2bfloat16_rn(y1 - __bfloat162float(h1)));
        L.z = bf16bits(__float2bfloat16_rn(y2 - __bfloat162float(h2)));
        L.w = bf16bits(__float2bfloat16_rn(y3 - __bfloat162float(h3)));
        reinterpret_cast<ushort4*>(h)[i] = H;
        reinterpret_cast<ushort4*>(l)[i] = L;
    }
}

// ---------------- launch ----------------
extern "C" void kernel_launch(void* const* d_in, const int* in_sizes, int n_in,
                              void* d_out, int out_size) {
    const float* x   = (const float*)d_in[0];
    const int*   ei  = (const int*)d_in[1];
    const float* W1  = (const float*)d_in[2];
    const float* as1 = (const float*)d_in[3];
    const float* ad1 = (const float*)d_in[4];
    const float* b1  = (const float*)d_in[5];
    const float* ga1 = (const float*)d_in[6];
    const float* be1 = (const float*)d_in[7];
    const float* W2  = (const float*)d_in[8];
    const float* as2 = (const float*)d_in[9];
    const float* ad2 = (const float*)d_in[10];
    const float* b2  = (const float*)d_in[11];
    const float* ga2 = (const float*)d_in[12];
    const float* be2 = (const float*)d_in[13];
    const float* W3  = (const float*)d_in[14];
    const float* as3 = (const float*)d_in[15];
    const float* ad3 = (const float*)d_in[16];
    const float* b3  = (const float*)d_in[17];
    float* out = (float*)d_out;

    float *bufA, *bufB;
    unsigned short *ah, *al, *wh, *wl;
    cudaGetSymbolAddress((void**)&bufA, g_bufA);
    cudaGetSymbolAddress((void**)&bufB, g_bufB);
    cudaGetSymbolAddress((void**)&ah, g_ah);
    cudaGetSymbolAddress((void**)&al, g_al);
    cudaGetSymbolAddress((void**)&wh, g_wh);
    cudaGetSymbolAddress((void**)&wl, g_wl);

    cudaFuncSetAttribute(gemm_cp, cudaFuncAttributeMaxDynamicSharedMemorySize,
                         SMEM_GEMM_BYTES);

    const dim3 gemmGrid(4, (NN + 63) / 64);

    hist_kernel<<<(ETOT + 255) / 256, 256>>>(ei);
    {
        int n4 = NN * IN_DIM / 4;
        splita_kernel<<<(n4 + 255) / 256, 256>>>(x, ah, al, n4);
    }
    splitw_kernel<<<(IN_DIM * HC + 255) / 256, 256>>>(W1, wh, wl, IN_DIM, HC, HC, WOFF1, 0);
    gemm_cp<<<gemmGrid, 256, SMEM_GEMM_BYTES>>>(
        NN, HC, HC, IN_DIM, ah, al, wh + WOFF1, wl + WOFF1, bufA,
        as1, ad1, HEADS, HIDC);
    scan_kernel<<<1, 1024>>>();
    scatter_kernel<<<(ETOT + 255) / 256, 256>>>(ei);

    // ----- layer 1 rest -----
    gather_fused<HEADS, HIDC><<<NN, 128>>>(bufA, b1, bufB, 1);
    bn_stats_kernel<<<(NN + 255) / 256, 512>>>(bufB);
    bn_final_kernel<<<1, 512>>>(ga1, be1);
    bn_apply_split_kernel<<<(NN * HC / 4 + 255) / 256, 256>>>(bufB, ah, al);

    // ----- layer 2 -----
    splitw_kernel<<<(HC * HC + 255) / 256, 256>>>(W2, wh, wl, HC, HC, HC, WOFF2, 0);
    gemm_cp<<<gemmGrid, 256, SMEM_GEMM_BYTES>>>(
        NN, HC, HC, HC, ah, al, wh + WOFF2, wl + WOFF2, bufA,
        as2, ad2, HEADS, HIDC);
    gather_fused<HEADS, HIDC><<<NN, 128>>>(bufA, b2, bufB, 1);
    bn_stats_kernel<<<(NN + 255) / 256, 512>>>(bufB);
    bn_final_kernel<<<1, 512>>>(ga2, be2);
    bn_apply_split_kernel<<<(NN * HC / 4 + 255) / 256, 256>>>(bufB, ah, al);

    // ----- layer 3 (W3 padded to 512 cols; H=1; zsd folded into splitw) -----
    splitw_kernel<<<(HC * 512 + 255) / 256, 256>>>(W3, wh, wl, HC, OUTD, 512, WOFF3, 1);
    gemm_cp<<<gemmGrid, 256, SMEM_GEMM_BYTES>>>(
        NN, OUTD, 512, HC, ah, al, wh + WOFF3, wl + WOFF3, bufA,
        as3, ad3, 1, OUTD);
    gather_fused<1, OUTD><<<NN, 128>>>(bufA, b3, out, 0);
}

// round 14
// speedup vs baseline: 1.0142x; 1.0142x over previous
#include <cuda_runtime.h>
#include <cuda_bf16.h>
#include <math.h>
#include <stdint.h>
#include <string.h>

#define NN 10000
#define EE 320000
#define ETOT (EE + NN)
#define IN_DIM 1280
#define HIDC 128
#define HEADS 4
#define HC 512
#define OUTD 500

#define WOFF1 0
#define WOFF2 (IN_DIM * HC)
#define WOFF3 (WOFF2 + HC * HC)
#define WTOT  (WOFF3 + HC * HC)

// ---------------- scratch (no allocations allowed) ----------------
__device__ float g_bufA[(size_t)NN * HC];
__device__ float g_bufB[(size_t)NN * HC];
__device__ __align__(16) unsigned short g_ah[(size_t)NN * IN_DIM];
__device__ __align__(16) unsigned short g_al[(size_t)NN * IN_DIM];
__device__ __align__(16) unsigned short g_wh[WTOT];
__device__ __align__(16) unsigned short g_wl[WTOT];
__device__ __align__(16) float g_s[NN * HEADS];
__device__ __align__(16) float g_dl[NN * HEADS];
__device__ int   g_deg[NN];          // zero at load; scan re-zeroes after use
__device__ int   g_rs[NN + 1];
__device__ int   g_cur[NN];
__device__ int   g_csrc[ETOT];
__device__ double g_sum[HC];
__device__ double g_sq[HC];
__device__ float g_scale[HC];
__device__ float g_shift[HC];

__device__ __forceinline__ unsigned short bf16bits(__nv_bfloat16 v) {
    unsigned short r;
    memcpy(&r, &v, 2);
    return r;
}

// ---------------- CSR build ----------------
__global__ void hist_kernel(const int* __restrict__ ei) {
    int e = blockIdx.x * blockDim.x + threadIdx.x;
    if (e < ETOT) {
        int dst = (e < EE) ? ei[EE + e] : (e - EE);
        atomicAdd(&g_deg[dst], 1);
    }
}

__global__ void scan_kernel() {
    __shared__ int sm[1024];
    int tid = threadIdx.x;
    const int per = (NN + 1023) / 1024;
    int b = tid * per;
    int e = min(b + per, NN);
    int local = 0;
    for (int i = b; i < e; i++) local += g_deg[i];
    sm[tid] = local;
    __syncthreads();
    for (int off = 1; off < 1024; off <<= 1) {
        int v = (tid >= off) ? sm[tid - off] : 0;
        __syncthreads();
        sm[tid] += v;
        __syncthreads();
    }
    int run = sm[tid] - local;
    for (int i = b; i < e; i++) {
        g_rs[i] = run;
        g_cur[i] = run;
        run += g_deg[i];
    }
    for (int i = b; i < e; i++) g_deg[i] = 0;
    if (tid == 1023) g_rs[NN] = run;
}

__global__ void scatter_kernel(const int* __restrict__ ei) {
    int e = blockIdx.x * blockDim.x + threadIdx.x;
    if (e < ETOT) {
        int src, dst;
        if (e < EE) { src = ei[e]; dst = ei[EE + e]; }
        else        { src = dst = e - EE; }
        int p = atomicAdd(&g_cur[dst], 1);
        g_csrc[p] = src;
    }
}

// ---------------- bf16 H/L pre-split ----------------
__global__ void splita_kernel(const float* __restrict__ x,
                              unsigned short* __restrict__ h,
                              unsigned short* __restrict__ l, int n4) {
    int i = blockIdx.x * blockDim.x + threadIdx.x;
    if (i < n4) {
        float4 v = reinterpret_cast<const float4*>(x)[i];
        __nv_bfloat16 hx = __float2bfloat16_rn(v.x);
        __nv_bfloat16 hy = __float2bfloat16_rn(v.y);
        __nv_bfloat16 hz = __float2bfloat16_rn(v.z);
        __nv_bfloat16 hw = __float2bfloat16_rn(v.w);
        ushort4 H, L;
        H.x = bf16bits(hx); H.y = bf16bits(hy); H.z = bf16bits(hz); H.w = bf16bits(hw);
        L.x = bf16bits(__float2bfloat16_rn(v.x - __bfloat162float(hx)));
        L.y = bf16bits(__float2bfloat16_rn(v.y - __bfloat162float(hy)));
        L.z = bf16bits(__float2bfloat16_rn(v.z - __bfloat162float(hz)));
        L.w = bf16bits(__float2bfloat16_rn(v.w - __bfloat162float(hw)));
        reinterpret_cast<ushort4*>(h)[i] = H;
        reinterpret_cast<ushort4*>(l)[i] = L;
    }
}

// weight split w/ optional column pad
__global__ void splitw_kernel(const float* __restrict__ B,
                              unsigned short* __restrict__ h,
                              unsigned short* __restrict__ l,
                              int K, int Ns, int Nd, int woff) {
    int i = blockIdx.x * blockDim.x + threadIdx.x;
    if (i < K * Nd) {
        int r = i / Nd, c = i - r * Nd;
        float v = (c < Ns) ? B[r * Ns + c] : 0.f;
        __nv_bfloat16 hh = __float2bfloat16_rn(v);
        h[woff + i] = bf16bits(hh);
        l[woff + i] = bf16bits(__float2bfloat16_rn(v - __bfloat162float(hh)));
    }
}

// =====================================================================
//  cp.async + ldmatrix bf16x3 GEMM, 64M x 128N tile, 3 CTAs/SM,
//  single barrier per k-tile; fused s/d epilogue.
// =====================================================================
__device__ __forceinline__ void mma_bf16(float* c, const uint32_t* a, const uint32_t* b) {
    asm volatile(
        "mma.sync.aligned.m16n8k16.row.col.f32.bf16.bf16.f32 "
        "{%0,%1,%2,%3}, {%4,%5,%6,%7}, {%8,%9}, {%0,%1,%2,%3};\n"
        : "+f"(c[0]), "+f"(c[1]), "+f"(c[2]), "+f"(c[3])
        : "r"(a[0]), "r"(a[1]), "r"(a[2]), "r"(a[3]), "r"(b[0]), "r"(b[1]));
}

__device__ __forceinline__ void ldsm4(uint32_t* r, uint32_t a) {
    asm volatile("ldmatrix.sync.aligned.m8n8.x4.shared.b16 {%0,%1,%2,%3},[%4];"
                 : "=r"(r[0]), "=r"(r[1]), "=r"(r[2]), "=r"(r[3]) : "r"(a));
}
__device__ __forceinline__ void ldsm4t(uint32_t* r, uint32_t a) {
    asm volatile("ldmatrix.sync.aligned.m8n8.x4.trans.shared.b16 {%0,%1,%2,%3},[%4];"
                 : "=r"(r[0]), "=r"(r[1]), "=r"(r[2]), "=r"(r[3]) : "r"(a));
}
__device__ __forceinline__ void cpa16(uint32_t s, const void* g, int vbytes) {
    asm volatile("cp.async.cg.shared.global [%0],[%1],16,%2;" :: "r"(s), "l"(g), "r"(vbytes));
}

#define GEMM_STAGE 27648
#define SMEM_GEMM_BYTES (2 * GEMM_STAGE)

__global__ __launch_bounds__(256, 3) void gemm_cp(int M, int N, int Nb, int K,
        const unsigned short* __restrict__ Ah, const unsigned short* __restrict__ Al,
        const unsigned short* __restrict__ Bh, const unsigned short* __restrict__ Bl,
        float* __restrict__ C,
        const float* __restrict__ asrc, const float* __restrict__ adst,
        int Hh, int Cc) {
    extern __shared__ __align__(16) unsigned char smp[];
    uint32_t sb = (uint32_t)__cvta_generic_to_shared(smp);

    const int tid = threadIdx.x;
    const int lane = tid & 31;
    const int warp = tid >> 5;
    const int g = lane >> 2;
    const int tq = lane & 3;
    const int warpM = warp & 1;
    const int warpN = warp >> 1;
    const int rowBase = blockIdx.y * 64;
    const int colBase = blockIdx.x * 128;
    const int numKT = K / 32;

    auto issueLoads = [&](int kt, int s) {
        uint32_t st = sb + s * GEMM_STAGE;
        {
            int row = tid >> 2, ch = tid & 3;
            int gr = rowBase + row;
            int v = (gr < M) ? 16 : 0;
            size_t goff = (size_t)((gr < M) ? gr : 0) * K + kt * 32 + ch * 8;
            uint32_t d = row * 80 + ch * 16;
            cpa16(st + d, Ah + goff, v);
            cpa16(st + 5120 + d, Al + goff, v);
        }
#pragma unroll
        for (int i = 0; i < 2; i++) {
            int idx = tid + i * 256;
            int row = idx >> 4, ch = idx & 15;
            size_t goff = (size_t)(kt * 32 + row) * Nb + colBase + ch * 8;
            uint32_t d = row * 272 + ch * 16;
            cpa16(st + 10240 + d, Bh + goff, 16);
            cpa16(st + 18944 + d, Bl + goff, 16);
        }
        asm volatile("cp.async.commit_group;");
    };

    float acc[2][4][4];
#pragma unroll
    for (int mt = 0; mt < 2; mt++)
#pragma unroll
        for (int nt = 0; nt < 4; nt++)
#pragma unroll
            for (int q = 0; q < 4; q++) acc[mt][nt][q] = 0.f;

    issueLoads(0, 0);

    for (int kt = 0; kt < numKT; kt++) {
        asm volatile("cp.async.wait_group 0;");
        __syncthreads();
        int cur = kt & 1;
        if (kt + 1 < numKT) issueLoads(kt + 1, cur ^ 1);

        uint32_t st = sb + cur * GEMM_STAGE;

#pragma unroll
        for (int ks = 0; ks < 2; ks++) {
            uint32_t aH[2][4], aL[2][4];
#pragma unroll
            for (int mt = 0; mt < 2; mt++) {
                uint32_t off = (uint32_t)(warpM * 32 + mt * 16 + (lane & 15)) * 80
                             + (ks * 16 + (lane >> 4) * 8) * 2;
                ldsm4(aH[mt], st + off);
                ldsm4(aL[mt], st + 5120 + off);
            }
#pragma unroll
            for (int ntp = 0; ntp < 2; ntp++) {
                uint32_t boff = (uint32_t)(ks * 16 + (lane & 15)) * 272
                              + (warpN * 32 + ntp * 16 + (lane >> 4) * 8) * 2;
                uint32_t bh[4], bl[4];
                ldsm4t(bh, st + 10240 + boff);
                ldsm4t(bl, st + 18944 + boff);
#pragma unroll
                for (int mt = 0; mt < 2; mt++) {
                    mma_bf16(acc[mt][ntp * 2 + 0], aH[mt], bh + 0);
                    mma_bf16(acc[mt][ntp * 2 + 1], aH[mt], bh + 2);
                    mma_bf16(acc[mt][ntp * 2 + 0], aL[mt], bh + 0);
                    mma_bf16(acc[mt][ntp * 2 + 1], aL[mt], bh + 2);
                    mma_bf16(acc[mt][ntp * 2 + 0], aH[mt], bl + 0);
                    mma_bf16(acc[mt][ntp * 2 + 1], aH[mt], bl + 2);
                }
            }
        }
    }
    __syncthreads();

    // ---- store C ----
#pragma unroll
    for (int mt = 0; mt < 2; mt++) {
        int r0 = rowBase + warpM * 32 + mt * 16 + g;
        int r1 = r0 + 8;
#pragma unroll
        for (int nt = 0; nt < 4; nt++) {
            int c0 = colBase + warpN * 32 + nt * 8 + tq * 2;
            if (r0 < M) {
                if (c0 < N)     C[(size_t)r0 * N + c0]     = acc[mt][nt][0];
                if (c0 + 1 < N) C[(size_t)r0 * N + c0 + 1] = acc[mt][nt][1];
            }
            if (r1 < M) {
                if (c0 < N)     C[(size_t)r1 * N + c0]     = acc[mt][nt][2];
                if (c0 + 1 < N) C[(size_t)r1 * N + c0 + 1] = acc[mt][nt][3];
            }
        }
    }

    // ---- fused s/d epilogue (CTA-local reduction) ----
    {
        float sp[2][2] = {{0.f, 0.f}, {0.f, 0.f}};
        float dp[2][2] = {{0.f, 0.f}, {0.f, 0.f}};
#pragma unroll
        for (int nt = 0; nt < 4; nt++) {
            int c0 = colBase + warpN * 32 + nt * 8 + tq * 2;
            if (c0 < N) {
                float a0 = asrc[c0];
                float d0 = adst[c0];
                float a1 = (c0 + 1 < N) ? asrc[c0 + 1] : 0.f;
                float d1 = (c0 + 1 < N) ? adst[c0 + 1] : 0.f;
#pragma unroll
                for (int mt = 0; mt < 2; mt++) {
                    sp[mt][0] += acc[mt][nt][0] * a0 + acc[mt][nt][1] * a1;
                    sp[mt][1] += acc[mt][nt][2] * a0 + acc[mt][nt][3] * a1;
                    dp[mt][0] += acc[mt][nt][0] * d0 + acc[mt][nt][1] * d1;
                    dp[mt][1] += acc[mt][nt][2] * d0 + acc[mt][nt][3] * d1;
                }
            }
        }
#pragma unroll
        for (int off = 1; off <= 2; off <<= 1) {
#pragma unroll
            for (int mt = 0; mt < 2; mt++)
#pragma unroll
                for (int rr = 0; rr < 2; rr++) {
                    sp[mt][rr] += __shfl_xor_sync(0xFFFFFFFF, sp[mt][rr], off);
                    dp[mt][rr] += __shfl_xor_sync(0xFFFFFFFF, dp[mt][rr], off);
                }
        }
        float* sredS = (float*)smp;          // [64][4]
        float* sredD = (float*)smp + 256;    // [64][4]
        if (tq == 0) {
#pragma unroll
            for (int mt = 0; mt < 2; mt++)
#pragma unroll
                for (int rr = 0; rr < 2; rr++) {
                    int rl = warpM * 32 + mt * 16 + rr * 8 + g;
                    sredS[rl * 4 + warpN] = sp[mt][rr];
                    sredD[rl * 4 + warpN] = dp[mt][rr];
                }
        }
        __syncthreads();
        if (tid < 64) {
            int r = rowBase + tid;
            if (r < M) {
                float ss = sredS[tid * 4] + sredS[tid * 4 + 1]
                         + sredS[tid * 4 + 2] + sredS[tid * 4 + 3];
                float dd = sredD[tid * 4] + sredD[tid * 4 + 1]
                         + sredD[tid * 4 + 2] + sredD[tid * 4 + 3];
                if (Cc == 128) {
                    g_s[r * Hh + blockIdx.x] = ss;
                    g_dl[r * Hh + blockIdx.x] = dd;
                } else {
                    atomicAdd(&g_s[r], ss);
                    atomicAdd(&g_dl[r], dd);
                }
            }
        }
    }
}

// ---------------- fused softmax + weighted gather per dst node ----------------
template <int H, int C>
__global__ __launch_bounds__(128) void gather_fused(const float* __restrict__ xp,
                                                    const float* __restrict__ bias,
                                                    float* __restrict__ out,
                                                    int bnzero) {
    constexpr int HCc = H * C;
    const int v = blockIdx.x;
    const int tid = threadIdx.x;
    const int lane = tid & 31;
    const int wid = tid >> 5;
    const int start = g_rs[v], end = g_rs[v + 1];
    const int deg = end - start;

    if (bnzero && v == 0) {
        for (int i = tid; i < HC; i += 128) { g_sum[i] = 0.0; g_sq[i] = 0.0; }
    }

    __shared__ float wsh[128 * H];
    __shared__ int ssh[128];
    __shared__ float red[4 * H];
    __shared__ float zish[H];

    float dv[H];
    if (H == 4) {
        float4 t = *reinterpret_cast<const float4*>(&g_dl[v * 4]);
        dv[0] = t.x; dv[1] = t.y; dv[2] = t.z; dv[3] = t.w;
    } else {
        dv[0] = g_dl[v];
    }

    const int c0 = tid * 4;
    const bool active = c0 < HCc;
    const int hh = active ? (c0 / C) : 0;
    float4 acc = make_float4(0.f, 0.f, 0.f, 0.f);

    auto gatherBatch = [&](int cnt, float zmul) {
        if (active) {
            int j = 0;
            for (; j + 16 <= cnt; j += 16) {
                float w[16];
                float4 xv[16];
#pragma unroll
                for (int q = 0; q < 16; q++) {
                    w[q] = wsh[(j + q) * H + hh] * zmul;
                    xv[q] = *reinterpret_cast<const float4*>(
                        xp + (size_t)ssh[j + q] * HCc + c0);
                }
#pragma unroll
                for (int q = 0; q < 16; q++) {
                    acc.x += w[q] * xv[q].x;
                    acc.y += w[q] * xv[q].y;
                    acc.z += w[q] * xv[q].z;
                    acc.w += w[q] * xv[q].w;
                }
            }
            for (; j + 8 <= cnt; j += 8) {
                float w[8];
                float4 xv[8];
#pragma unroll
                for (int q = 0; q < 8; q++) {
                    w[q] = wsh[(j + q) * H + hh] * zmul;
                    xv[q] = *reinterpret_cast<const float4*>(
                        xp + (size_t)ssh[j + q] * HCc + c0);
                }
#pragma unroll
                for (int q = 0; q < 8; q++) {
                    acc.x += w[q] * xv[q].x;
                    acc.y += w[q] * xv[q].y;
                    acc.z += w[q] * xv[q].z;
                    acc.w += w[q] * xv[q].w;
                }
            }
            for (; j < cnt; j++) {
                float w = wsh[j * H + hh] * zmul;
                const float4 xv = *reinterpret_cast<const float4*>(
                    xp + (size_t)ssh[j] * HCc + c0);
                acc.x += w * xv.x;
                acc.y += w * xv.y;
                acc.z += w * xv.z;
                acc.w += w * xv.w;
            }
        }
    };

    if (deg <= 128) {
        float ex[H];
#pragma unroll
        for (int h = 0; h < H; h++) ex[h] = 0.f;
        if (tid < deg) {
            int se = g_csrc[start + tid];
            ssh[tid] = se;
            float sv[H];
            if (H == 4) {
                float4 t = *reinterpret_cast<const float4*>(&g_s[se * 4]);
                sv[0] = t.x; sv[1] = t.y; sv[2] = t.z; sv[3] = t.w;
            } else {
                sv[0] = g_s[se];
            }
#pragma unroll
            for (int h = 0; h < H; h++) {
                float l = sv[h] + dv[h];
                l = l > 0.f ? l : 0.2f * l;
                ex[h] = __expf(l);
                wsh[tid * H + h] = ex[h];
            }
        }
#pragma unroll
        for (int h = 0; h < H; h++)
#pragma unroll
            for (int off = 16; off > 0; off >>= 1)
                ex[h] += __shfl_xor_sync(0xFFFFFFFF, ex[h], off);
        if (lane == 0) {
#pragma unroll
            for (int h = 0; h < H; h++) red[wid * H + h] = ex[h];
        }
        __syncthreads();
        if (tid < H)
            zish[tid] = 1.f / (red[tid] + red[H + tid] + red[2 * H + tid] + red[3 * H + tid]);
        __syncthreads();
        float zmul = zish[hh];
        gatherBatch(deg, zmul);
    } else {
        float lsum[H];
#pragma unroll
        for (int h = 0; h < H; h++) lsum[h] = 0.f;
        for (int e = start + tid; e < end; e += 128) {
            int se = g_csrc[e];
            float sv[H];
            if (H == 4) {
                float4 t = *reinterpret_cast<const float4*>(&g_s[se * 4]);
                sv[0] = t.x; sv[1] = t.y; sv[2] = t.z; sv[3] = t.w;
            } else {
                sv[0] = g_s[se];
            }
#pragma unroll
            for (int h = 0; h < H; h++) {
                float l = sv[h] + dv[h];
                l = l > 0.f ? l : 0.2f * l;
                lsum[h] += __expf(l);
            }
        }
#pragma unroll
        for (int h = 0; h < H; h++)
#pragma unroll
            for (int off = 16; off > 0; off >>= 1)
                lsum[h] += __shfl_xor_sync(0xFFFFFFFF, lsum[h], off);
        if (lane == 0) {
#pragma unroll
            for (int h = 0; h < H; h++) red[wid * H + h] = lsum[h];
        }
        __syncthreads();
        if (tid < H)
            zish[tid] = 1.f / (red[tid] + red[H + tid] + red[2 * H + tid] + red[3 * H + tid]);
        __syncthreads();
        float zmul = zish[hh];

        for (int base = start; base < end; base += 128) {
            int cnt = min(128, end - base);
            __syncthreads();
            if (tid < cnt) {
                int se = g_csrc[base + tid];
                ssh[tid] = se;
                float sv[H];
                if (H == 4) {
                    float4 t = *reinterpret_cast<const float4*>(&g_s[se * 4]);
                    sv[0] = t.x; sv[1] = t.y; sv[2] = t.z; sv[3] = t.w;
                } else {
                    sv[0] = g_s[se];
                }
#pragma unroll
                for (int h = 0; h < H; h++) {
                    float l = sv[h] + dv[h];
                    l = l > 0.f ? l : 0.2f * l;
                    wsh[tid * H + h] = __expf(l);
                }
            }
            __syncthreads();
            gatherBatch(cnt, zmul);
        }
    }

    if (active) {
        const float4 bb = *reinterpret_cast<const float4*>(bias + c0);
        float* o = out + (size_t)v * HCc + c0;
        o[0] = acc.x + bb.x;
        o[1] = acc.y + bb.y;
        o[2] = acc.z + bb.z;
        o[3] = acc.w + bb.w;
    }
}

// ---------------- BatchNorm (+ELU) ----------------
__global__ void bn_stats_kernel(const float* __restrict__ x) {
    int c = threadIdx.x;
    int r0 = blockIdx.x * 256;
    int r1 = min(r0 + 256, NN);
    double s = 0.0, q = 0.0;
    for (int r = r0; r < r1; r++) {
        float v = x[(size_t)r * HC + c];
        s += v;
        q += (double)v * (double)v;
    }
    atomicAdd(&g_sum[c], s);
    atomicAdd(&g_sq[c], q);
}

__global__ void bn_final_kernel(const float* __restrict__ gam,
                                const float* __restrict__ bet) {
    int c = threadIdx.x;
    if (c < HC) {
        double mu = g_sum[c] / NN;
        double var = g_sq[c] / NN - mu * mu;
        float sc = rsqrtf((float)var + 1e-5f) * gam[c];
        g_scale[c] = sc;
        g_shift[c] = bet[c] - (float)mu * sc;
    }
}

// BN+ELU apply; optional zeroing of g_s/g_dl (before layer-3 gemm atomics)
__global__ void bn_apply_split_kernel(const float* __restrict__ x,
                                      unsigned short* __restrict__ h,
                                      unsigned short* __restrict__ l,
                                      int zsd) {
    int i = blockIdx.x * blockDim.x + threadIdx.x;
    if (zsd && i < NN * HEADS) { g_s[i] = 0.f; g_dl[i] = 0.f; }
    const int n4 = NN * HC / 4;
    if (i < n4) {
        float4 v = reinterpret_cast<const float4*>(x)[i];
        int c0 = (i * 4) & (HC - 1);
        float y0 = v.x * g_scale[c0 + 0] + g_shift[c0 + 0];
        float y1 = v.y * g_scale[c0 + 1] + g_shift[c0 + 1];
        float y2 = v.z * g_scale[c0 + 2] + g_shift[c0 + 2];
        float y3 = v.w * g_scale[c0 + 3] + g_shift[c0 + 3];
        y0 = y0 > 0.f ? y0 : expm1f(y0);
        y1 = y1 > 0.f ? y1 : expm1f(y1);
        y2 = y2 > 0.f ? y2 : expm1f(y2);
        y3 = y3 > 0.f ? y3 : expm1f(y3);
        __nv_bfloat16 h0 = __float2bfloat16_rn(y0);
        __nv_bfloat16 h1 = __float2bfloat16_rn(y1);
        __nv_bfloat16 h2 = __float2bfloat16_rn(y2);
        __nv_bfloat16 h3 = __float2bfloat16_rn(y3);
        ushort4 H, L;
        H.x = bf16bits(h0); H.y = bf16bits(h1); H.z = bf16bits(h2); H.w = bf16bits(h3);
        L.x = bf16bits(__float2bfloat16_rn(y0 - __bfloat162float(h0)));
        L.y = bf16bits(__float2bfloat16_rn(y1 - __bfloat162float(h1)));
        L.z = bf16bits(__float2bfloat16_rn(y2 - __bfloat162float(h2)));
        L.w = bf16bits(__float2bfloat16_rn(y3 - __bfloat162float(h3)));
        reinterpret_cast<ushort4*>(h)[i] = H;
        reinterpret_cast<ushort4*>(l)[i] = L;
    }
}

// ---------------- launch ----------------
extern "C" void kernel_launch(void* const* d_in, const int* in_sizes, int n_in,
                              void* d_out, int out_size) {
    const float* x   = (const float*)d_in[0];
    const int*   ei  = (const int*)d_in[1];
    const float* W1  = (const float*)d_in[2];
    const float* as1 = (const float*)d_in[3];
    const float* ad1 = (const float*)d_in[4];
    const float* b1  = (const float*)d_in[5];
    const float* ga1 = (const float*)d_in[6];
    const float* be1 = (const float*)d_in[7];
    const float* W2  = (const float*)d_in[8];
    const float* as2 = (const float*)d_in[9];
    const float* ad2 = (const float*)d_in[10];
    const float* b2  = (const float*)d_in[11];
    const float* ga2 = (const float*)d_in[12];
    const float* be2 = (const float*)d_in[13];
    const float* W3  = (const float*)d_in[14];
    const float* as3 = (const float*)d_in[15];
    const float* ad3 = (const float*)d_in[16];
    const float* b3  = (const float*)d_in[17];
    float* out = (float*)d_out;

    float *bufA, *bufB;
    unsigned short *ah, *al, *wh, *wl;
    cudaGetSymbolAddress((void**)&bufA, g_bufA);
    cudaGetSymbolAddress((void**)&bufB, g_bufB);
    cudaGetSymbolAddress((void**)&ah, g_ah);
    cudaGetSymbolAddress((void**)&al, g_al);
    cudaGetSymbolAddress((void**)&wh, g_wh);
    cudaGetSymbolAddress((void**)&wl, g_wl);

    cudaFuncSetAttribute(gemm_cp, cudaFuncAttributeMaxDynamicSharedMemorySize,
                         SMEM_GEMM_BYTES);

    // lazy one-time side stream + fork/join events (host objects only;
    // identical launched work every call)
    static cudaStream_t s2 = nullptr;
    static cudaEvent_t evFork = nullptr, evCsr = nullptr, evW = nullptr;
    if (!s2) {
        cudaStreamCreateWithFlags(&s2, cudaStreamNonBlocking);
        cudaEventCreateWithFlags(&evFork, cudaEventDisableTiming);
        cudaEventCreateWithFlags(&evCsr, cudaEventDisableTiming);
        cudaEventCreateWithFlags(&evW, cudaEventDisableTiming);
    }

    const dim3 gemmGrid(4, (NN + 63) / 64);

    // ---- fork: CSR build + layer-2/3 weight splits on side stream ----
    cudaEventRecord(evFork, 0);
    cudaStreamWaitEvent(s2, evFork, 0);
    hist_kernel<<<(ETOT + 255) / 256, 256, 0, s2>>>(ei);
    scan_kernel<<<1, 1024, 0, s2>>>();
    scatter_kernel<<<(ETOT + 255) / 256, 256, 0, s2>>>(ei);
    cudaEventRecord(evCsr, s2);
    splitw_kernel<<<(HC * HC + 255) / 256, 256, 0, s2>>>(W2, wh, wl, HC, HC, HC, WOFF2);
    splitw_kernel<<<(HC * 512 + 255) / 256, 256, 0, s2>>>(W3, wh, wl, HC, OUTD, 512, WOFF3);
    cudaEventRecord(evW, s2);

    // ---- main stream: layer 1 ----
    {
        int n4 = NN * IN_DIM / 4;
        splita_kernel<<<(n4 + 255) / 256, 256>>>(x, ah, al, n4);
    }
    splitw_kernel<<<(IN_DIM * HC + 255) / 256, 256>>>(W1, wh, wl, IN_DIM, HC, HC, WOFF1);
    gemm_cp<<<gemmGrid, 256, SMEM_GEMM_BYTES>>>(
        NN, HC, HC, IN_DIM, ah, al, wh + WOFF1, wl + WOFF1, bufA,
        as1, ad1, HEADS, HIDC);

    cudaStreamWaitEvent(0, evCsr, 0);   // CSR ready before gather
    gather_fused<HEADS, HIDC><<<NN, 128>>>(bufA, b1, bufB, 1);
    bn_stats_kernel<<<(NN + 255) / 256, 512>>>(bufB);
    bn_final_kernel<<<1, 512>>>(ga1, be1);
    bn_apply_split_kernel<<<(NN * HC / 4 + 255) / 256, 256>>>(bufB, ah, al, 0);

    // ---- layer 2 ----
    cudaStreamWaitEvent(0, evW, 0);     // W2/W3 splits ready
    gemm_cp<<<gemmGrid, 256, SMEM_GEMM_BYTES>>>(
        NN, HC, HC, HC, ah, al, wh + WOFF2, wl + WOFF2, bufA,
        as2, ad2, HEADS, HIDC);
    gather_fused<HEADS, HIDC><<<NN, 128>>>(bufA, b2, bufB, 1);
    bn_stats_kernel<<<(NN + 255) / 256, 512>>>(bufB);
    bn_final_kernel<<<1, 512>>>(ga2, be2);
    bn_apply_split_kernel<<<(NN * HC / 4 + 255) / 256, 256>>>(bufB, ah, al, 1);

    // ---- layer 3 (W3 padded to 512 cols; H=1) ----
    gemm_cp<<<gemmGrid, 256, SMEM_GEMM_BYTES>>>(
        NN, OUTD, 512, HC, ah, al, wh + WOFF3, wl + WOFF3, bufA,
        as3, ad3, 1, OUTD);
    gather_fused<1, OUTD><<<NN, 128>>>(bufA, b3, out, 0);
}

// round 16
// speedup vs baseline: 1.0295x; 1.0151x over previous
#include <cuda_runtime.h>
#include <cuda_bf16.h>
#include <math.h>
#include <stdint.h>
#include <string.h>

#define NN 10000
#define EE 320000
#define ETOT (EE + NN)
#define IN_DIM 1280
#define HIDC 128
#define HEADS 4
#define HC 512
#define OUTD 500

#define WOFF1 0
#define WOFF2 (IN_DIM * HC)
#define WOFF3 (WOFF2 + HC * HC)
#define WTOT  (WOFF3 + HC * HC)

// ---------------- scratch (no allocations allowed) ----------------
__device__ float g_bufA[(size_t)NN * HC];
__device__ float g_bufB[(size_t)NN * HC];
__device__ __align__(16) unsigned short g_ah[(size_t)NN * IN_DIM];
__device__ __align__(16) unsigned short g_al[(size_t)NN * IN_DIM];
__device__ __align__(16) unsigned short g_wh[WTOT];
__device__ __align__(16) unsigned short g_wl[WTOT];
__device__ __align__(16) float g_s[NN * HEADS];
__device__ __align__(16) float g_dl[NN * HEADS];
__device__ int   g_deg[NN];          // zero at load; scan re-zeroes after use
__device__ int   g_rs[NN + 1];
__device__ int   g_cur[NN];
__device__ int   g_csrc[ETOT];
__device__ double g_sum[HC];
__device__ double g_sq[HC];
__device__ float g_scale[HC];
__device__ float g_shift[HC];

__device__ __forceinline__ unsigned short bf16bits(__nv_bfloat16 v) {
    unsigned short r;
    memcpy(&r, &v, 2);
    return r;
}

// ---------------- CSR build ----------------
__global__ void hist_kernel(const int* __restrict__ ei) {
    int e = blockIdx.x * blockDim.x + threadIdx.x;
    if (e < ETOT) {
        int dst = (e < EE) ? ei[EE + e] : (e - EE);
        atomicAdd(&g_deg[dst], 1);
    }
}

__global__ void scan_kernel() {
    __shared__ int sm[1024];
    int tid = threadIdx.x;
    const int per = (NN + 1023) / 1024;
    int b = tid * per;
    int e = min(b + per, NN);
    int local = 0;
    for (int i = b; i < e; i++) local += g_deg[i];
    sm[tid] = local;
    __syncthreads();
    for (int off = 1; off < 1024; off <<= 1) {
        int v = (tid >= off) ? sm[tid - off] : 0;
        __syncthreads();
        sm[tid] += v;
        __syncthreads();
    }
    int run = sm[tid] - local;
    for (int i = b; i < e; i++) {
        g_rs[i] = run;
        g_cur[i] = run;
        run += g_deg[i];
    }
    for (int i = b; i < e; i++) g_deg[i] = 0;
    if (tid == 1023) g_rs[NN] = run;
}

__global__ void scatter_kernel(const int* __restrict__ ei) {
    int e = blockIdx.x * blockDim.x + threadIdx.x;
    if (e < ETOT) {
        int src, dst;
        if (e < EE) { src = ei[e]; dst = ei[EE + e]; }
        else        { src = dst = e - EE; }
        int p = atomicAdd(&g_cur[dst], 1);
        g_csrc[p] = src;
    }
}

// ---------------- bf16 H/L pre-split ----------------
__global__ void splita_kernel(const float* __restrict__ x,
                              unsigned short* __restrict__ h,
                              unsigned short* __restrict__ l, int n4) {
    int i = blockIdx.x * blockDim.x + threadIdx.x;
    if (i < n4) {
        float4 v = reinterpret_cast<const float4*>(x)[i];
        __nv_bfloat16 hx = __float2bfloat16_rn(v.x);
        __nv_bfloat16 hy = __float2bfloat16_rn(v.y);
        __nv_bfloat16 hz = __float2bfloat16_rn(v.z);
        __nv_bfloat16 hw = __float2bfloat16_rn(v.w);
        ushort4 H, L;
        H.x = bf16bits(hx); H.y = bf16bits(hy); H.z = bf16bits(hz); H.w = bf16bits(hw);
        L.x = bf16bits(__float2bfloat16_rn(v.x - __bfloat162float(hx)));
        L.y = bf16bits(__float2bfloat16_rn(v.y - __bfloat162float(hy)));
        L.z = bf16bits(__float2bfloat16_rn(v.z - __bfloat162float(hz)));
        L.w = bf16bits(__float2bfloat16_rn(v.w - __bfloat162float(hw)));
        reinterpret_cast<ushort4*>(h)[i] = H;
        reinterpret_cast<ushort4*>(l)[i] = L;
    }
}

// weight split w/ optional column pad
__global__ void splitw_kernel(const float* __restrict__ B,
                              unsigned short* __restrict__ h,
                              unsigned short* __restrict__ l,
                              int K, int Ns, int Nd, int woff) {
    int i = blockIdx.x * blockDim.x + threadIdx.x;
    if (i < K * Nd) {
        int r = i / Nd, c = i - r * Nd;
        float v = (c < Ns) ? B[r * Ns + c] : 0.f;
        __nv_bfloat16 hh = __float2bfloat16_rn(v);
        h[woff + i] = bf16bits(hh);
        l[woff + i] = bf16bits(__float2bfloat16_rn(v - __bfloat162float(hh)));
    }
}

// =====================================================================
//  cp.async + ldmatrix bf16x3 GEMM, 96M x 128N tile, 192 thr, 3 CTAs/SM
//  (single-wave grid: 4 x 105 = 420 CTAs <= 444 slots).
//  Fused s/d epilogue: direct store when one head per col-block.
// =====================================================================
__device__ __forceinline__ void mma_bf16(float* c, const uint32_t* a, const uint32_t* b) {
    asm volatile(
        "mma.sync.aligned.m16n8k16.row.col.f32.bf16.bf16.f32 "
        "{%0,%1,%2,%3}, {%4,%5,%6,%7}, {%8,%9}, {%0,%1,%2,%3};\n"
        : "+f"(c[0]), "+f"(c[1]), "+f"(c[2]), "+f"(c[3])
        : "r"(a[0]), "r"(a[1]), "r"(a[2]), "r"(a[3]), "r"(b[0]), "r"(b[1]));
}

__device__ __forceinline__ void ldsm4(uint32_t* r, uint32_t a) {
    asm volatile("ldmatrix.sync.aligned.m8n8.x4.shared.b16 {%0,%1,%2,%3},[%4];"
                 : "=r"(r[0]), "=r"(r[1]), "=r"(r[2]), "=r"(r[3]) : "r"(a));
}
__device__ __forceinline__ void ldsm4t(uint32_t* r, uint32_t a) {
    asm volatile("ldmatrix.sync.aligned.m8n8.x4.trans.shared.b16 {%0,%1,%2,%3},[%4];"
                 : "=r"(r[0]), "=r"(r[1]), "=r"(r[2]), "=r"(r[3]) : "r"(a));
}
__device__ __forceinline__ void cpa16(uint32_t s, const void* g, int vbytes) {
    asm volatile("cp.async.cg.shared.global [%0],[%1],16,%2;" :: "r"(s), "l"(g), "r"(vbytes));
}

// per-stage: AH 7680 | AL 7680 | BH 8704 | BL 8704 = 32768; 2 stages
#define GEMM_STAGE 32768
#define SMEM_GEMM_BYTES (2 * GEMM_STAGE)
#define TM 96

__global__ __launch_bounds__(192, 3) void gemm_cp(int M, int N, int Nb, int K,
        const unsigned short* __restrict__ Ah, const unsigned short* __restrict__ Al,
        const unsigned short* __restrict__ Bh, const unsigned short* __restrict__ Bl,
        float* __restrict__ C,
        const float* __restrict__ asrc, const float* __restrict__ adst,
        int Hh, int Cc) {
    extern __shared__ __align__(16) unsigned char smp[];
    uint32_t sb = (uint32_t)__cvta_generic_to_shared(smp);

    const int tid = threadIdx.x;
    const int lane = tid & 31;
    const int warp = tid >> 5;          // 0..5
    const int g = lane >> 2;
    const int tq = lane & 3;
    const int warpM = warp % 3;         // 3 bands of 32 rows
    const int warpN = warp / 3;         // 2 bands of 64 cols
    const int rowBase = blockIdx.y * TM;
    const int colBase = blockIdx.x * 128;
    const int numKT = K / 32;

    auto issueLoads = [&](int kt, int s) {
        uint32_t st = sb + s * GEMM_STAGE;
        // A: 384 chunks of 16B per limb (96 rows x 4 chunks)
#pragma unroll
        for (int i = 0; i < 2; i++) {
            int idx = tid + i * 192;
            int row = idx >> 2, ch = idx & 3;
            int gr = rowBase + row;
            int v = (gr < M) ? 16 : 0;
            size_t goff = (size_t)((gr < M) ? gr : 0) * K + kt * 32 + ch * 8;
            uint32_t d = row * 80 + ch * 16;
            cpa16(st + d, Ah + goff, v);
            cpa16(st + 7680 + d, Al + goff, v);
        }
        // B: 512 chunks per limb (32 k-rows x 16 chunks)
#pragma unroll
        for (int i = 0; i < 3; i++) {
            int idx = tid + i * 192;
            if (idx < 512) {
                int row = idx >> 4, ch = idx & 15;
                size_t goff = (size_t)(kt * 32 + row) * Nb + colBase + ch * 8;
                uint32_t d = row * 272 + ch * 16;
                cpa16(st + 15360 + d, Bh + goff, 16);
                cpa16(st + 24064 + d, Bl + goff, 16);
            }
        }
        asm volatile("cp.async.commit_group;");
    };

    float acc[2][8][4];
#pragma unroll
    for (int mt = 0; mt < 2; mt++)
#pragma unroll
        for (int nt = 0; nt < 8; nt++)
#pragma unroll
            for (int q = 0; q < 4; q++) acc[mt][nt][q] = 0.f;

    issueLoads(0, 0);

    for (int kt = 0; kt < numKT; kt++) {
        asm volatile("cp.async.wait_group 0;");
        __syncthreads();
        int cur = kt & 1;
        if (kt + 1 < numKT) issueLoads(kt + 1, cur ^ 1);

        uint32_t st = sb + cur * GEMM_STAGE;

#pragma unroll
        for (int ks = 0; ks < 2; ks++) {
            uint32_t aH[2][4], aL[2][4];
#pragma unroll
            for (int mt = 0; mt < 2; mt++) {
                uint32_t off = (uint32_t)(warpM * 32 + mt * 16 + (lane & 15)) * 80
                             + (ks * 16 + (lane >> 4) * 8) * 2;
                ldsm4(aH[mt], st + off);
                ldsm4(aL[mt], st + 7680 + off);
            }
#pragma unroll
            for (int ntp = 0; ntp < 4; ntp++) {
                uint32_t boff = (uint32_t)(ks * 16 + (lane & 15)) * 272
                              + (warpN * 64 + ntp * 16 + (lane >> 4) * 8) * 2;
                uint32_t bh[4], bl[4];
                ldsm4t(bh, st + 15360 + boff);
                ldsm4t(bl, st + 24064 + boff);
#pragma unroll
                for (int mt = 0; mt < 2; mt++) {
                    mma_bf16(acc[mt][ntp * 2 + 0], aH[mt], bh + 0);
                    mma_bf16(acc[mt][ntp * 2 + 1], aH[mt], bh + 2);
                    mma_bf16(acc[mt][ntp * 2 + 0], aL[mt], bh + 0);
                    mma_bf16(acc[mt][ntp * 2 + 1], aL[mt], bh + 2);
                    mma_bf16(acc[mt][ntp * 2 + 0], aH[mt], bl + 0);
                    mma_bf16(acc[mt][ntp * 2 + 1], aH[mt], bl + 2);
                }
            }
        }
    }
    __syncthreads();

    // ---- store C ----
#pragma unroll
    for (int mt = 0; mt < 2; mt++) {
        int r0 = rowBase + warpM * 32 + mt * 16 + g;
        int r1 = r0 + 8;
#pragma unroll
        for (int nt = 0; nt < 8; nt++) {
            int c0 = colBase + warpN * 64 + nt * 8 + tq * 2;
            if (r0 < M) {
                if (c0 < N)     C[(size_t)r0 * N + c0]     = acc[mt][nt][0];
                if (c0 + 1 < N) C[(size_t)r0 * N + c0 + 1] = acc[mt][nt][1];
            }
            if (r1 < M) {
                if (c0 < N)     C[(size_t)r1 * N + c0]     = acc[mt][nt][2];
                if (c0 + 1 < N) C[(size_t)r1 * N + c0 + 1] = acc[mt][nt][3];
            }
        }
    }

    // ---- fused s/d epilogue (CTA-local reduction) ----
    {
        float sp[2][2] = {{0.f, 0.f}, {0.f, 0.f}};
        float dp[2][2] = {{0.f, 0.f}, {0.f, 0.f}};
#pragma unroll
        for (int nt = 0; nt < 8; nt++) {
            int c0 = colBase + warpN * 64 + nt * 8 + tq * 2;
            if (c0 < N) {
                float a0 = asrc[c0];
                float d0 = adst[c0];
                float a1 = (c0 + 1 < N) ? asrc[c0 + 1] : 0.f;
                float d1 = (c0 + 1 < N) ? adst[c0 + 1] : 0.f;
#pragma unroll
                for (int mt = 0; mt < 2; mt++) {
                    sp[mt][0] += acc[mt][nt][0] * a0 + acc[mt][nt][1] * a1;
                    sp[mt][1] += acc[mt][nt][2] * a0 + acc[mt][nt][3] * a1;
                    dp[mt][0] += acc[mt][nt][0] * d0 + acc[mt][nt][1] * d1;
                    dp[mt][1] += acc[mt][nt][2] * d0 + acc[mt][nt][3] * d1;
                }
            }
        }
#pragma unroll
        for (int off = 1; off <= 2; off <<= 1) {
#pragma unroll
            for (int mt = 0; mt < 2; mt++)
#pragma unroll
                for (int rr = 0; rr < 2; rr++) {
                    sp[mt][rr] += __shfl_xor_sync(0xFFFFFFFF, sp[mt][rr], off);
                    dp[mt][rr] += __shfl_xor_sync(0xFFFFFFFF, dp[mt][rr], off);
                }
        }
        float* sredS = (float*)smp;          // [96][2]
        float* sredD = (float*)smp + 192;    // [96][2]
        if (tq == 0) {
#pragma unroll
            for (int mt = 0; mt < 2; mt++)
#pragma unroll
                for (int rr = 0; rr < 2; rr++) {
                    int rl = warpM * 32 + mt * 16 + rr * 8 + g;
                    sredS[rl * 2 + warpN] = sp[mt][rr];
                    sredD[rl * 2 + warpN] = dp[mt][rr];
                }
        }
        __syncthreads();
        if (tid < TM) {
            int r = rowBase + tid;
            if (r < M) {
                float ss = sredS[tid * 2] + sredS[tid * 2 + 1];
                float dd = sredD[tid * 2] + sredD[tid * 2 + 1];
                if (Cc == 128) {
                    g_s[r * Hh + blockIdx.x] = ss;
                    g_dl[r * Hh + blockIdx.x] = dd;
                } else {
                    atomicAdd(&g_s[r], ss);
                    atomicAdd(&g_dl[r], dd);
                }
            }
        }
    }
}

// ---------------- fused softmax + weighted gather per dst node ----------------
template <int H, int C>
__global__ __launch_bounds__(128) void gather_fused(const float* __restrict__ xp,
                                                    const float* __restrict__ bias,
                                                    float* __restrict__ out,
                                                    int bnzero) {
    constexpr int HCc = H * C;
    const int v = blockIdx.x;
    const int tid = threadIdx.x;
    const int lane = tid & 31;
    const int wid = tid >> 5;
    const int start = g_rs[v], end = g_rs[v + 1];
    const int deg = end - start;

    if (bnzero && v == 0) {
        for (int i = tid; i < HC; i += 128) { g_sum[i] = 0.0; g_sq[i] = 0.0; }
    }

    __shared__ float wsh[128 * H];
    __shared__ int ssh[128];
    __shared__ float red[4 * H];
    __shared__ float zish[H];

    float dv[H];
    if (H == 4) {
        float4 t = *reinterpret_cast<const float4*>(&g_dl[v * 4]);
        dv[0] = t.x; dv[1] = t.y; dv[2] = t.z; dv[3] = t.w;
    } else {
        dv[0] = g_dl[v];
    }

    const int c0 = tid * 4;
    const bool active = c0 < HCc;
    const int hh = active ? (c0 / C) : 0;
    float4 acc = make_float4(0.f, 0.f, 0.f, 0.f);

    auto gatherBatch = [&](int cnt, float zmul) {
        if (active) {
            int j = 0;
            for (; j + 16 <= cnt; j += 16) {
                float w[16];
                float4 xv[16];
#pragma unroll
                for (int q = 0; q < 16; q++) {
                    w[q] = wsh[(j + q) * H + hh] * zmul;
                    xv[q] = *reinterpret_cast<const float4*>(
                        xp + (size_t)ssh[j + q] * HCc + c0);
                }
#pragma unroll
                for (int q = 0; q < 16; q++) {
                    acc.x += w[q] * xv[q].x;
                    acc.y += w[q] * xv[q].y;
                    acc.z += w[q] * xv[q].z;
                    acc.w += w[q] * xv[q].w;
                }
            }
            for (; j + 8 <= cnt; j += 8) {
                float w[8];
                float4 xv[8];
#pragma unroll
                for (int q = 0; q < 8; q++) {
                    w[q] = wsh[(j + q) * H + hh] * zmul;
                    xv[q] = *reinterpret_cast<const float4*>(
                        xp + (size_t)ssh[j + q] * HCc + c0);
                }
#pragma unroll
                for (int q = 0; q < 8; q++) {
                    acc.x += w[q] * xv[q].x;
                    acc.y += w[q] * xv[q].y;
                    acc.z += w[q] * xv[q].z;
                    acc.w += w[q] * xv[q].w;
                }
            }
            for (; j < cnt; j++) {
                float w = wsh[j * H + hh] * zmul;
                const float4 xv = *reinterpret_cast<const float4*>(
                    xp + (size_t)ssh[j] * HCc + c0);
                acc.x += w * xv.x;
                acc.y += w * xv.y;
                acc.z += w * xv.z;
                acc.w += w * xv.w;
            }
        }
    };

    if (deg <= 128) {
        float ex[H];
#pragma unroll
        for (int h = 0; h < H; h++) ex[h] = 0.f;
        if (tid < deg) {
            int se = g_csrc[start + tid];
            ssh[tid] = se;
            float sv[H];
            if (H == 4) {
                float4 t = *reinterpret_cast<const float4*>(&g_s[se * 4]);
                sv[0] = t.x; sv[1] = t.y; sv[2] = t.z; sv[3] = t.w;
            } else {
                sv[0] = g_s[se];
            }
#pragma unroll
            for (int h = 0; h < H; h++) {
                float l = sv[h] + dv[h];
                l = l > 0.f ? l : 0.2f * l;
                ex[h] = __expf(l);
                wsh[tid * H + h] = ex[h];
            }
        }
#pragma unroll
        for (int h = 0; h < H; h++)
#pragma unroll
            for (int off = 16; off > 0; off >>= 1)
                ex[h] += __shfl_xor_sync(0xFFFFFFFF, ex[h], off);
        if (lane == 0) {
#pragma unroll
            for (int h = 0; h < H; h++) red[wid * H + h] = ex[h];
        }
        __syncthreads();
        if (tid < H)
            zish[tid] = 1.f / (red[tid] + red[H + tid] + red[2 * H + tid] + red[3 * H + tid]);
        __syncthreads();
        float zmul = zish[hh];
        gatherBatch(deg, zmul);
    } else {
        float lsum[H];
#pragma unroll
        for (int h = 0; h < H; h++) lsum[h] = 0.f;
        for (int e = start + tid; e < end; e += 128) {
            int se = g_csrc[e];
            float sv[H];
            if (H == 4) {
                float4 t = *reinterpret_cast<const float4*>(&g_s[se * 4]);
                sv[0] = t.x; sv[1] = t.y; sv[2] = t.z; sv[3] = t.w;
            } else {
                sv[0] = g_s[se];
            }
#pragma unroll
            for (int h = 0; h < H; h++) {
                float l = sv[h] + dv[h];
                l = l > 0.f ? l : 0.2f * l;
                lsum[h] += __expf(l);
            }
        }
#pragma unroll
        for (int h = 0; h < H; h++)
#pragma unroll
            for (int off = 16; off > 0; off >>= 1)
                lsum[h] += __shfl_xor_sync(0xFFFFFFFF, lsum[h], off);
        if (lane == 0) {
#pragma unroll
            for (int h = 0; h < H; h++) red[wid * H + h] = lsum[h];
        }
        __syncthreads();
        if (tid < H)
            zish[tid] = 1.f / (red[tid] + red[H + tid] + red[2 * H + tid] + red[3 * H + tid]);
        __syncthreads();
        float zmul = zish[hh];

        for (int base = start; base < end; base += 128) {
            int cnt = min(128, end - base);
            __syncthreads();
            if (tid < cnt) {
                int se = g_csrc[base + tid];
                ssh[tid] = se;
                float sv[H];
                if (H == 4) {
                    float4 t = *reinterpret_cast<const float4*>(&g_s[se * 4]);
                    sv[0] = t.x; sv[1] = t.y; sv[2] = t.z; sv[3] = t.w;
                } else {
                    sv[0] = g_s[se];
                }
#pragma unroll
                for (int h = 0; h < H; h++) {
                    float l = sv[h] + dv[h];
                    l = l > 0.f ? l : 0.2f * l;
                    wsh[tid * H + h] = __expf(l);
                }
            }
            __syncthreads();
            gatherBatch(cnt, zmul);
        }
    }

    if (active) {
        const float4 bb = *reinterpret_cast<const float4*>(bias + c0);
        float* o = out + (size_t)v * HCc + c0;
        o[0] = acc.x + bb.x;
        o[1] = acc.y + bb.y;
        o[2] = acc.z + bb.z;
        o[3] = acc.w + bb.w;
    }
}

// ---------------- BatchNorm (+ELU) ----------------
__global__ void bn_stats_kernel(const float* __restrict__ x) {
    int c = threadIdx.x;
    int r0 = blockIdx.x * 256;
    int r1 = min(r0 + 256, NN);
    double s = 0.0, q = 0.0;
    for (int r = r0; r < r1; r++) {
        float v = x[(size_t)r * HC + c];
        s += v;
        q += (double)v * (double)v;
    }
    atomicAdd(&g_sum[c], s);
    atomicAdd(&g_sq[c], q);
}

__global__ void bn_final_kernel(const float* __restrict__ gam,
                                const float* __restrict__ bet) {
    int c = threadIdx.x;
    if (c < HC) {
        double mu = g_sum[c] / NN;
        double var = g_sq[c] / NN - mu * mu;
        float sc = rsqrtf((float)var + 1e-5f) * gam[c];
        g_scale[c] = sc;
        g_shift[c] = bet[c] - (float)mu * sc;
    }
}

// BN+ELU apply; optional zeroing of g_s/g_dl (before layer-3 gemm atomics)
__global__ void bn_apply_split_kernel(const float* __restrict__ x,
                                      unsigned short* __restrict__ h,
                                      unsigned short* __restrict__ l,
                                      int zsd) {
    int i = blockIdx.x * blockDim.x + threadIdx.x;
    if (zsd && i < NN * HEADS) { g_s[i] = 0.f; g_dl[i] = 0.f; }
    const int n4 = NN * HC / 4;
    if (i < n4) {
        float4 v = reinterpret_cast<const float4*>(x)[i];
        int c0 = (i * 4) & (HC - 1);
        float y0 = v.x * g_scale[c0 + 0] + g_shift[c0 + 0];
        float y1 = v.y * g_scale[c0 + 1] + g_shift[c0 + 1];
        float y2 = v.z * g_scale[c0 + 2] + g_shift[c0 + 2];
        float y3 = v.w * g_scale[c0 + 3] + g_shift[c0 + 3];
        y0 = y0 > 0.f ? y0 : expm1f(y0);
        y1 = y1 > 0.f ? y1 : expm1f(y1);
        y2 = y2 > 0.f ? y2 : expm1f(y2);
        y3 = y3 > 0.f ? y3 : expm1f(y3);
        __nv_bfloat16 h0 = __float2bfloat16_rn(y0);
        __nv_bfloat16 h1 = __float2bfloat16_rn(y1);
        __nv_bfloat16 h2 = __float2bfloat16_rn(y2);
        __nv_bfloat16 h3 = __float2bfloat16_rn(y3);
        ushort4 H, L;
        H.x = bf16bits(h0); H.y = bf16bits(h1); H.z = bf16bits(h2); H.w = bf16bits(h3);
        L.x = bf16bits(__float2bfloat16_rn(y0 - __bfloat162float(h0)));
        L.y = bf16bits(__float2bfloat16_rn(y1 - __bfloat162float(h1)));
        L.z = bf16bits(__float2bfloat16_rn(y2 - __bfloat162float(h2)));
        L.w = bf16bits(__float2bfloat16_rn(y3 - __bfloat162float(h3)));
        reinterpret_cast<ushort4*>(h)[i] = H;
        reinterpret_cast<ushort4*>(l)[i] = L;
    }
}

// ---------------- launch ----------------
extern "C" void kernel_launch(void* const* d_in, const int* in_sizes, int n_in,
                              void* d_out, int out_size) {
    const float* x   = (const float*)d_in[0];
    const int*   ei  = (const int*)d_in[1];
    const float* W1  = (const float*)d_in[2];
    const float* as1 = (const float*)d_in[3];
    const float* ad1 = (const float*)d_in[4];
    const float* b1  = (const float*)d_in[5];
    const float* ga1 = (const float*)d_in[6];
    const float* be1 = (const float*)d_in[7];
    const float* W2  = (const float*)d_in[8];
    const float* as2 = (const float*)d_in[9];
    const float* ad2 = (const float*)d_in[10];
    const float* b2  = (const float*)d_in[11];
    const float* ga2 = (const float*)d_in[12];
    const float* be2 = (const float*)d_in[13];
    const float* W3  = (const float*)d_in[14];
    const float* as3 = (const float*)d_in[15];
    const float* ad3 = (const float*)d_in[16];
    const float* b3  = (const float*)d_in[17];
    float* out = (float*)d_out;

    float *bufA, *bufB;
    unsigned short *ah, *al, *wh, *wl;
    cudaGetSymbolAddress((void**)&bufA, g_bufA);
    cudaGetSymbolAddress((void**)&bufB, g_bufB);
    cudaGetSymbolAddress((void**)&ah, g_ah);
    cudaGetSymbolAddress((void**)&al, g_al);
    cudaGetSymbolAddress((void**)&wh, g_wh);
    cudaGetSymbolAddress((void**)&wl, g_wl);

    cudaFuncSetAttribute(gemm_cp, cudaFuncAttributeMaxDynamicSharedMemorySize,
                         SMEM_GEMM_BYTES);

    static cudaStream_t s2 = nullptr;
    static cudaEvent_t evFork = nullptr, evCsr = nullptr, evW = nullptr;
    if (!s2) {
        cudaStreamCreateWithFlags(&s2, cudaStreamNonBlocking);
        cudaEventCreateWithFlags(&evFork, cudaEventDisableTiming);
        cudaEventCreateWithFlags(&evCsr, cudaEventDisableTiming);
        cudaEventCreateWithFlags(&evW, cudaEventDisableTiming);
    }

    const dim3 gemmGrid(4, (NN + TM - 1) / TM);   // 4 x 105 = 420 CTAs, single wave

    // ---- fork: CSR build + layer-2/3 weight splits on side stream ----
    cudaEventRecord(evFork, 0);
    cudaStreamWaitEvent(s2, evFork, 0);
    hist_kernel<<<(ETOT + 255) / 256, 256, 0, s2>>>(ei);
    scan_kernel<<<1, 1024, 0, s2>>>();
    scatter_kernel<<<(ETOT + 255) / 256, 256, 0, s2>>>(ei);
    cudaEventRecord(evCsr, s2);
    splitw_kernel<<<(HC * HC + 255) / 256, 256, 0, s2>>>(W2, wh, wl, HC, HC, HC, WOFF2);
    splitw_kernel<<<(HC * 512 + 255) / 256, 256, 0, s2>>>(W3, wh, wl, HC, OUTD, 512, WOFF3);
    cudaEventRecord(evW, s2);

    // ---- main stream: layer 1 ----
    {
        int n4 = NN * IN_DIM / 4;
        splita_kernel<<<(n4 + 255) / 256, 256>>>(x, ah, al, n4);
    }
    splitw_kernel<<<(IN_DIM * HC + 255) / 256, 256>>>(W1, wh, wl, IN_DIM, HC, HC, WOFF1);
    gemm_cp<<<gemmGrid, 192, SMEM_GEMM_BYTES>>>(
        NN, HC, HC, IN_DIM, ah, al, wh + WOFF1, wl + WOFF1, bufA,
        as1, ad1, HEADS, HIDC);

    cudaStreamWaitEvent(0, evCsr, 0);
    gather_fused<HEADS, HIDC><<<NN, 128>>>(bufA, b1, bufB, 1);
    bn_stats_kernel<<<(NN + 255) / 256, 512>>>(bufB);
    bn_final_kernel<<<1, 512>>>(ga1, be1);
    bn_apply_split_kernel<<<(NN * HC / 4 + 255) / 256, 256>>>(bufB, ah, al, 0);

    // ---- layer 2 ----
    cudaStreamWaitEvent(0, evW, 0);
    gemm_cp<<<gemmGrid, 192, SMEM_GEMM_BYTES>>>(
        NN, HC, HC, HC, ah, al, wh + WOFF2, wl + WOFF2, bufA,
        as2, ad2, HEADS, HIDC);
    gather_fused<HEADS, HIDC><<<NN, 128>>>(bufA, b2, bufB, 1);
    bn_stats_kernel<<<(NN + 255) / 256, 512>>>(bufB);
    bn_final_kernel<<<1, 512>>>(ga2, be2);
    bn_apply_split_kernel<<<(NN * HC / 4 + 255) / 256, 256>>>(bufB, ah, al, 1);

    // ---- layer 3 (W3 padded to 512 cols; H=1) ----
    gemm_cp<<<gemmGrid, 192, SMEM_GEMM_BYTES>>>(
        NN, OUTD, 512, HC, ah, al, wh + WOFF3, wl + WOFF3, bufA,
        as3, ad3, 1, OUTD);
    gather_fused<1, OUTD><<<NN, 128>>>(bufA, b3, out, 0);
}

// round 17
// speedup vs baseline: 1.0527x; 1.0226x over previous
#include <cuda_runtime.h>
#include <cuda_bf16.h>
#include <math.h>
#include <stdint.h>
#include <string.h>

#define NN 10000
#define EE 320000
#define ETOT (EE + NN)
#define IN_DIM 1280
#define HIDC 128
#define HEADS 4
#define HC 512
#define OUTD 500

#define WOFF1 0
#define WOFF2 (IN_DIM * HC)
#define WOFF3 (WOFF2 + HC * HC)
#define WTOT  (WOFF3 + HC * HC)

// ---------------- scratch (no allocations allowed) ----------------
__device__ float g_bufA[(size_t)NN * HC];
__device__ float g_bufB[(size_t)NN * HC];
__device__ __align__(16) unsigned short g_ah[(size_t)NN * IN_DIM];
__device__ __align__(16) unsigned short g_al[(size_t)NN * IN_DIM];
__device__ __align__(16) unsigned short g_wh[WTOT];
__device__ __align__(16) unsigned short g_wl[WTOT];
__device__ __align__(16) float g_s[NN * HEADS];
__device__ __align__(16) float g_dl[NN * HEADS];
__device__ int   g_deg[NN];          // zero at load; scan re-zeroes after use
__device__ int   g_rs[NN + 1];
__device__ int   g_cur[NN];
__device__ int   g_csrc[ETOT];
__device__ double g_sum[HC];
__device__ double g_sq[HC];
__device__ float g_scale[HC];
__device__ float g_shift[HC];
__device__ int   g_bnctr;            // static zero-init; reset by last block

__device__ __forceinline__ unsigned short bf16bits(__nv_bfloat16 v) {
    unsigned short r;
    memcpy(&r, &v, 2);
    return r;
}

// ---------------- CSR build ----------------
__global__ void hist_kernel(const int* __restrict__ ei) {
    int e = blockIdx.x * blockDim.x + threadIdx.x;
    if (e < ETOT) {
        int dst = (e < EE) ? ei[EE + e] : (e - EE);
        atomicAdd(&g_deg[dst], 1);
    }
}

__global__ void scan_kernel() {
    __shared__ int sm[1024];
    int tid = threadIdx.x;
    const int per = (NN + 1023) / 1024;
    int b = tid * per;
    int e = min(b + per, NN);
    int local = 0;
    for (int i = b; i < e; i++) local += g_deg[i];
    sm[tid] = local;
    __syncthreads();
    for (int off = 1; off < 1024; off <<= 1) {
        int v = (tid >= off) ? sm[tid - off] : 0;
        __syncthreads();
        sm[tid] += v;
        __syncthreads();
    }
    int run = sm[tid] - local;
    for (int i = b; i < e; i++) {
        g_rs[i] = run;
        g_cur[i] = run;
        run += g_deg[i];
    }
    for (int i = b; i < e; i++) g_deg[i] = 0;
    if (tid == 1023) g_rs[NN] = run;
}

__global__ void scatter_kernel(const int* __restrict__ ei) {
    int e = blockIdx.x * blockDim.x + threadIdx.x;
    if (e < ETOT) {
        int src, dst;
        if (e < EE) { src = ei[e]; dst = ei[EE + e]; }
        else        { src = dst = e - EE; }
        int p = atomicAdd(&g_cur[dst], 1);
        g_csrc[p] = src;
    }
}

// ---------------- bf16 H/L pre-split ----------------
__global__ void splita_kernel(const float* __restrict__ x,
                              unsigned short* __restrict__ h,
                              unsigned short* __restrict__ l, int n4) {
    int i = blockIdx.x * blockDim.x + threadIdx.x;
    if (i < n4) {
        float4 v = reinterpret_cast<const float4*>(x)[i];
        __nv_bfloat16 hx = __float2bfloat16_rn(v.x);
        __nv_bfloat16 hy = __float2bfloat16_rn(v.y);
        __nv_bfloat16 hz = __float2bfloat16_rn(v.z);
        __nv_bfloat16 hw = __float2bfloat16_rn(v.w);
        ushort4 H, L;
        H.x = bf16bits(hx); H.y = bf16bits(hy); H.z = bf16bits(hz); H.w = bf16bits(hw);
        L.x = bf16bits(__float2bfloat16_rn(v.x - __bfloat162float(hx)));
        L.y = bf16bits(__float2bfloat16_rn(v.y - __bfloat162float(hy)));
        L.z = bf16bits(__float2bfloat16_rn(v.z - __bfloat162float(hz)));
        L.w = bf16bits(__float2bfloat16_rn(v.w - __bfloat162float(hw)));
        reinterpret_cast<ushort4*>(h)[i] = H;
        reinterpret_cast<ushort4*>(l)[i] = L;
    }
}

// weight split w/ optional column pad
__global__ void splitw_kernel(const float* __restrict__ B,
                              unsigned short* __restrict__ h,
                              unsigned short* __restrict__ l,
                              int K, int Ns, int Nd, int woff) {
    int i = blockIdx.x * blockDim.x + threadIdx.x;
    if (i < K * Nd) {
        int r = i / Nd, c = i - r * Nd;
        float v = (c < Ns) ? B[r * Ns + c] : 0.f;
        __nv_bfloat16 hh = __float2bfloat16_rn(v);
        h[woff + i] = bf16bits(hh);
        l[woff + i] = bf16bits(__float2bfloat16_rn(v - __bfloat162float(hh)));
    }
}

// =====================================================================
//  cp.async + ldmatrix bf16x3 GEMM, 96M x 128N tile, 192 thr, 3 CTAs/SM
// =====================================================================
__device__ __forceinline__ void mma_bf16(float* c, const uint32_t* a, const uint32_t* b) {
    asm volatile(
        "mma.sync.aligned.m16n8k16.row.col.f32.bf16.bf16.f32 "
        "{%0,%1,%2,%3}, {%4,%5,%6,%7}, {%8,%9}, {%0,%1,%2,%3};\n"
        : "+f"(c[0]), "+f"(c[1]), "+f"(c[2]), "+f"(c[3])
        : "r"(a[0]), "r"(a[1]), "r"(a[2]), "r"(a[3]), "r"(b[0]), "r"(b[1]));
}

__device__ __forceinline__ void ldsm4(uint32_t* r, uint32_t a) {
    asm volatile("ldmatrix.sync.aligned.m8n8.x4.shared.b16 {%0,%1,%2,%3},[%4];"
                 : "=r"(r[0]), "=r"(r[1]), "=r"(r[2]), "=r"(r[3]) : "r"(a));
}
__device__ __forceinline__ void ldsm4t(uint32_t* r, uint32_t a) {
    asm volatile("ldmatrix.sync.aligned.m8n8.x4.trans.shared.b16 {%0,%1,%2,%3},[%4];"
                 : "=r"(r[0]), "=r"(r[1]), "=r"(r[2]), "=r"(r[3]) : "r"(a));
}
__device__ __forceinline__ void cpa16(uint32_t s, const void* g, int vbytes) {
    asm volatile("cp.async.cg.shared.global [%0],[%1],16,%2;" :: "r"(s), "l"(g), "r"(vbytes));
}

#define GEMM_STAGE 32768
#define SMEM_GEMM_BYTES (2 * GEMM_STAGE)
#define TM 96

__global__ __launch_bounds__(192, 3) void gemm_cp(int M, int N, int Nb, int K,
        const unsigned short* __restrict__ Ah, const unsigned short* __restrict__ Al,
        const unsigned short* __restrict__ Bh, const unsigned short* __restrict__ Bl,
        float* __restrict__ C,
        const float* __restrict__ asrc, const float* __restrict__ adst,
        int Hh, int Cc) {
    extern __shared__ __align__(16) unsigned char smp[];
    uint32_t sb = (uint32_t)__cvta_generic_to_shared(smp);

    const int tid = threadIdx.x;
    const int lane = tid & 31;
    const int warp = tid >> 5;
    const int g = lane >> 2;
    const int tq = lane & 3;
    const int warpM = warp % 3;
    const int warpN = warp / 3;
    const int rowBase = blockIdx.y * TM;
    const int colBase = blockIdx.x * 128;
    const int numKT = K / 32;

    auto issueLoads = [&](int kt, int s) {
        uint32_t st = sb + s * GEMM_STAGE;
#pragma unroll
        for (int i = 0; i < 2; i++) {
            int idx = tid + i * 192;
            int row = idx >> 2, ch = idx & 3;
            int gr = rowBase + row;
            int v = (gr < M) ? 16 : 0;
            size_t goff = (size_t)((gr < M) ? gr : 0) * K + kt * 32 + ch * 8;
            uint32_t d = row * 80 + ch * 16;
            cpa16(st + d, Ah + goff, v);
            cpa16(st + 7680 + d, Al + goff, v);
        }
#pragma unroll
        for (int i = 0; i < 3; i++) {
            int idx = tid + i * 192;
            if (idx < 512) {
                int row = idx >> 4, ch = idx & 15;
                size_t goff = (size_t)(kt * 32 + row) * Nb + colBase + ch * 8;
                uint32_t d = row * 272 + ch * 16;
                cpa16(st + 15360 + d, Bh + goff, 16);
                cpa16(st + 24064 + d, Bl + goff, 16);
            }
        }
        asm volatile("cp.async.commit_group;");
    };

    float acc[2][8][4];
#pragma unroll
    for (int mt = 0; mt < 2; mt++)
#pragma unroll
        for (int nt = 0; nt < 8; nt++)
#pragma unroll
            for (int q = 0; q < 4; q++) acc[mt][nt][q] = 0.f;

    issueLoads(0, 0);

    for (int kt = 0; kt < numKT; kt++) {
        asm volatile("cp.async.wait_group 0;");
        __syncthreads();
        int cur = kt & 1;
        if (kt + 1 < numKT) issueLoads(kt + 1, cur ^ 1);

        uint32_t st = sb + cur * GEMM_STAGE;

#pragma unroll
        for (int ks = 0; ks < 2; ks++) {
            uint32_t aH[2][4], aL[2][4];
#pragma unroll
            for (int mt = 0; mt < 2; mt++) {
                uint32_t off = (uint32_t)(warpM * 32 + mt * 16 + (lane & 15)) * 80
                             + (ks * 16 + (lane >> 4) * 8) * 2;
                ldsm4(aH[mt], st + off);
                ldsm4(aL[mt], st + 7680 + off);
            }
#pragma unroll
            for (int ntp = 0; ntp < 4; ntp++) {
                uint32_t boff = (uint32_t)(ks * 16 + (lane & 15)) * 272
                              + (warpN * 64 + ntp * 16 + (lane >> 4) * 8) * 2;
                uint32_t bh[4], bl[4];
                ldsm4t(bh, st + 15360 + boff);
                ldsm4t(bl, st + 24064 + boff);
#pragma unroll
                for (int mt = 0; mt < 2; mt++) {
                    mma_bf16(acc[mt][ntp * 2 + 0], aH[mt], bh + 0);
                    mma_bf16(acc[mt][ntp * 2 + 1], aH[mt], bh + 2);
                    mma_bf16(acc[mt][ntp * 2 + 0], aL[mt], bh + 0);
                    mma_bf16(acc[mt][ntp * 2 + 1], aL[mt], bh + 2);
                    mma_bf16(acc[mt][ntp * 2 + 0], aH[mt], bl + 0);
                    mma_bf16(acc[mt][ntp * 2 + 1], aH[mt], bl + 2);
                }
            }
        }
    }
    __syncthreads();

    // ---- store C ----
#pragma unroll
    for (int mt = 0; mt < 2; mt++) {
        int r0 = rowBase + warpM * 32 + mt * 16 + g;
        int r1 = r0 + 8;
#pragma unroll
        for (int nt = 0; nt < 8; nt++) {
            int c0 = colBase + warpN * 64 + nt * 8 + tq * 2;
            if (r0 < M) {
                if (c0 < N)     C[(size_t)r0 * N + c0]     = acc[mt][nt][0];
                if (c0 + 1 < N) C[(size_t)r0 * N + c0 + 1] = acc[mt][nt][1];
            }
            if (r1 < M) {
                if (c0 < N)     C[(size_t)r1 * N + c0]     = acc[mt][nt][2];
                if (c0 + 1 < N) C[(size_t)r1 * N + c0 + 1] = acc[mt][nt][3];
            }
        }
    }

    // ---- fused s/d epilogue (CTA-local reduction) ----
    {
        float sp[2][2] = {{0.f, 0.f}, {0.f, 0.f}};
        float dp[2][2] = {{0.f, 0.f}, {0.f, 0.f}};
#pragma unroll
        for (int nt = 0; nt < 8; nt++) {
            int c0 = colBase + warpN * 64 + nt * 8 + tq * 2;
            if (c0 < N) {
                float a0 = asrc[c0];
                float d0 = adst[c0];
                float a1 = (c0 + 1 < N) ? asrc[c0 + 1] : 0.f;
                float d1 = (c0 + 1 < N) ? adst[c0 + 1] : 0.f;
#pragma unroll
                for (int mt = 0; mt < 2; mt++) {
                    sp[mt][0] += acc[mt][nt][0] * a0 + acc[mt][nt][1] * a1;
                    sp[mt][1] += acc[mt][nt][2] * a0 + acc[mt][nt][3] * a1;
                    dp[mt][0] += acc[mt][nt][0] * d0 + acc[mt][nt][1] * d1;
                    dp[mt][1] += acc[mt][nt][2] * d0 + acc[mt][nt][3] * d1;
                }
            }
        }
#pragma unroll
        for (int off = 1; off <= 2; off <<= 1) {
#pragma unroll
            for (int mt = 0; mt < 2; mt++)
#pragma unroll
                for (int rr = 0; rr < 2; rr++) {
                    sp[mt][rr] += __shfl_xor_sync(0xFFFFFFFF, sp[mt][rr], off);
                    dp[mt][rr] += __shfl_xor_sync(0xFFFFFFFF, dp[mt][rr], off);
                }
        }
        float* sredS = (float*)smp;          // [96][2]
        float* sredD = (float*)smp + 192;    // [96][2]
        if (tq == 0) {
#pragma unroll
            for (int mt = 0; mt < 2; mt++)
#pragma unroll
                for (int rr = 0; rr < 2; rr++) {
                    int rl = warpM * 32 + mt * 16 + rr * 8 + g;
                    sredS[rl * 2 + warpN] = sp[mt][rr];
                    sredD[rl * 2 + warpN] = dp[mt][rr];
                }
        }
        __syncthreads();
        if (tid < TM) {
            int r = rowBase + tid;
            if (r < M) {
                float ss = sredS[tid * 2] + sredS[tid * 2 + 1];
                float dd = sredD[tid * 2] + sredD[tid * 2 + 1];
                if (Cc == 128) {
                    g_s[r * Hh + blockIdx.x] = ss;
                    g_dl[r * Hh + blockIdx.x] = dd;
                } else {
                    atomicAdd(&g_s[r], ss);
                    atomicAdd(&g_dl[r], dd);
                }
            }
        }
    }
}

// ---------------- fused softmax + weighted gather per dst node ----------------
template <int H, int C>
__global__ __launch_bounds__(128) void gather_fused(const float* __restrict__ xp,
                                                    const float* __restrict__ bias,
                                                    float* __restrict__ out,
                                                    int bnzero) {
    constexpr int HCc = H * C;
    const int v = blockIdx.x;
    const int tid = threadIdx.x;
    const int lane = tid & 31;
    const int wid = tid >> 5;
    const int start = g_rs[v], end = g_rs[v + 1];
    const int deg = end - start;

    if (bnzero && v == 0) {
        for (int i = tid; i < HC; i += 128) { g_sum[i] = 0.0; g_sq[i] = 0.0; }
    }

    __shared__ float wsh[128 * H];
    __shared__ int ssh[128];
    __shared__ float red[4 * H];
    __shared__ float zish[H];

    float dv[H];
    if (H == 4) {
        float4 t = *reinterpret_cast<const float4*>(&g_dl[v * 4]);
        dv[0] = t.x; dv[1] = t.y; dv[2] = t.z; dv[3] = t.w;
    } else {
        dv[0] = g_dl[v];
    }

    const int c0 = tid * 4;
    const bool active = c0 < HCc;
    const int hh = active ? (c0 / C) : 0;
    float4 acc = make_float4(0.f, 0.f, 0.f, 0.f);

    auto gatherBatch = [&](int cnt, float zmul) {
        if (active) {
            int j = 0;
            for (; j + 16 <= cnt; j += 16) {
                float w[16];
                float4 xv[16];
#pragma unroll
                for (int q = 0; q < 16; q++) {
                    w[q] = wsh[(j + q) * H + hh] * zmul;
                    xv[q] = *reinterpret_cast<const float4*>(
                        xp + (size_t)ssh[j + q] * HCc + c0);
                }
#pragma unroll
                for (int q = 0; q < 16; q++) {
                    acc.x += w[q] * xv[q].x;
                    acc.y += w[q] * xv[q].y;
                    acc.z += w[q] * xv[q].z;
                    acc.w += w[q] * xv[q].w;
                }
            }
            for (; j + 8 <= cnt; j += 8) {
                float w[8];
                float4 xv[8];
#pragma unroll
                for (int q = 0; q < 8; q++) {
                    w[q] = wsh[(j + q) * H + hh] * zmul;
                    xv[q] = *reinterpret_cast<const float4*>(
                        xp + (size_t)ssh[j + q] * HCc + c0);
                }
#pragma unroll
                for (int q = 0; q < 8; q++) {
                    acc.x += w[q] * xv[q].x;
                    acc.y += w[q] * xv[q].y;
                    acc.z += w[q] * xv[q].z;
                    acc.w += w[q] * xv[q].w;
                }
            }
            for (; j < cnt; j++) {
                float w = wsh[j * H + hh] * zmul;
                const float4 xv = *reinterpret_cast<const float4*>(
                    xp + (size_t)ssh[j] * HCc + c0);
                acc.x += w * xv.x;
                acc.y += w * xv.y;
                acc.z += w * xv.z;
                acc.w += w * xv.w;
            }
        }
    };

    if (deg <= 128) {
        float ex[H];
#pragma unroll
        for (int h = 0; h < H; h++) ex[h] = 0.f;
        if (tid < deg) {
            int se = g_csrc[start + tid];
            ssh[tid] = se;
            float sv[H];
            if (H == 4) {
                float4 t = *reinterpret_cast<const float4*>(&g_s[se * 4]);
                sv[0] = t.x; sv[1] = t.y; sv[2] = t.z; sv[3] = t.w;
            } else {
                sv[0] = g_s[se];
            }
#pragma unroll
            for (int h = 0; h < H; h++) {
                float l = sv[h] + dv[h];
                l = l > 0.f ? l : 0.2f * l;
                ex[h] = __expf(l);
                wsh[tid * H + h] = ex[h];
            }
        }
#pragma unroll
        for (int h = 0; h < H; h++)
#pragma unroll
            for (int off = 16; off > 0; off >>= 1)
                ex[h] += __shfl_xor_sync(0xFFFFFFFF, ex[h], off);
        if (lane == 0) {
#pragma unroll
            for (int h = 0; h < H; h++) red[wid * H + h] = ex[h];
        }
        __syncthreads();
        if (tid < H)
            zish[tid] = 1.f / (red[tid] + red[H + tid] + red[2 * H + tid] + red[3 * H + tid]);
        __syncthreads();
        float zmul = zish[hh];
        gatherBatch(deg, zmul);
    } else {
        float lsum[H];
#pragma unroll
        for (int h = 0; h < H; h++) lsum[h] = 0.f;
        for (int e = start + tid; e < end; e += 128) {
            int se = g_csrc[e];
            float sv[H];
            if (H == 4) {
                float4 t = *reinterpret_cast<const float4*>(&g_s[se * 4]);
                sv[0] = t.x; sv[1] = t.y; sv[2] = t.z; sv[3] = t.w;
            } else {
                sv[0] = g_s[se];
            }
#pragma unroll
            for (int h = 0; h < H; h++) {
                float l = sv[h] + dv[h];
                l = l > 0.f ? l : 0.2f * l;
                lsum[h] += __expf(l);
            }
        }
#pragma unroll
        for (int h = 0; h < H; h++)
#pragma unroll
            for (int off = 16; off > 0; off >>= 1)
                lsum[h] += __shfl_xor_sync(0xFFFFFFFF, lsum[h], off);
        if (lane == 0) {
#pragma unroll
            for (int h = 0; h < H; h++) red[wid * H + h] = lsum[h];
        }
        __syncthreads();
        if (tid < H)
            zish[tid] = 1.f / (red[tid] + red[H + tid] + red[2 * H + tid] + red[3 * H + tid]);
        __syncthreads();
        float zmul = zish[hh];

        for (int base = start; base < end; base += 128) {
            int cnt = min(128, end - base);
            __syncthreads();
            if (tid < cnt) {
                int se = g_csrc[base + tid];
                ssh[tid] = se;
                float sv[H];
                if (H == 4) {
                    float4 t = *reinterpret_cast<const float4*>(&g_s[se * 4]);
                    sv[0] = t.x; sv[1] = t.y; sv[2] = t.z; sv[3] = t.w;
                } else {
                    sv[0] = g_s[se];
                }
#pragma unroll
                for (int h = 0; h < H; h++) {
                    float l = sv[h] + dv[h];
                    l = l > 0.f ? l : 0.2f * l;
                    wsh[tid * H + h] = __expf(l);
                }
            }
            __syncthreads();
            gatherBatch(cnt, zmul);
        }
    }

    if (active) {
        const float4 bb = *reinterpret_cast<const float4*>(bias + c0);
        float* o = out + (size_t)v * HCc + c0;
        o[0] = acc.x + bb.x;
        o[1] = acc.y + bb.y;
        o[2] = acc.z + bb.z;
        o[3] = acc.w + bb.w;
    }
}

// ---------------- BatchNorm stats + fused finalization ----------------
__global__ void bn_stats_kernel(const float* __restrict__ x,
                                const float* __restrict__ gam,
                                const float* __restrict__ bet) {
    int c = threadIdx.x;
    int r0 = blockIdx.x * 256;
    int r1 = min(r0 + 256, NN);
    double s = 0.0, q = 0.0;
    for (int r = r0; r < r1; r++) {
        float v = x[(size_t)r * HC + c];
        s += v;
        q += (double)v * (double)v;
    }
    atomicAdd(&g_sum[c], s);
    atomicAdd(&g_sq[c], q);

    // last-block finalization (replaces bn_final kernel)
    __shared__ int isLast;
    __threadfence();
    if (c == 0) {
        int t = atomicAdd(&g_bnctr, 1);
        isLast = (t == (int)gridDim.x - 1);
    }
    __syncthreads();
    if (isLast) {
        double mu = g_sum[c] / NN;
        double var = g_sq[c] / NN - mu * mu;
        float sc = rsqrtf((float)var + 1e-5f) * gam[c];
        g_scale[c] = sc;
        g_shift[c] = bet[c] - (float)mu * sc;
        if (c == 0) g_bnctr = 0;
    }
}

// BN+ELU apply; optional zeroing of g_s/g_dl (before layer-3 gemm atomics)
__global__ void bn_apply_split_kernel(const float* __restrict__ x,
                                      unsigned short* __restrict__ h,
                                      unsigned short* __restrict__ l,
                                      int zsd) {
    int i = blockIdx.x * blockDim.x + threadIdx.x;
    if (zsd && i < NN * HEADS) { g_s[i] = 0.f; g_dl[i] = 0.f; }
    const int n4 = NN * HC / 4;
    if (i < n4) {
        float4 v = reinterpret_cast<const float4*>(x)[i];
        int c0 = (i * 4) & (HC - 1);
        float y0 = v.x * g_scale[c0 + 0] + g_shift[c0 + 0];
        float y1 = v.y * g_scale[c0 + 1] + g_shift[c0 + 1];
        float y2 = v.z * g_scale[c0 + 2] + g_shift[c0 + 2];
        float y3 = v.w * g_scale[c0 + 3] + g_shift[c0 + 3];
        y0 = y0 > 0.f ? y0 : expm1f(y0);
        y1 = y1 > 0.f ? y1 : expm1f(y1);
        y2 = y2 > 0.f ? y2 : expm1f(y2);
        y3 = y3 > 0.f ? y3 : expm1f(y3);
        __nv_bfloat16 h0 = __float2bfloat16_rn(y0);
        __nv_bfloat16 h1 = __float2bfloat16_rn(y1);
        __nv_bfloat16 h2 = __float2bfloat16_rn(y2);
        __nv_bfloat16 h3 = __float2bfloat16_rn(y3);
        ushort4 H, L;
        H.x = bf16bits(h0); H.y = bf16bits(h1); H.z = bf16bits(h2); H.w = bf16bits(h3);
        L.x = bf16bits(__float2bfloat16_rn(y0 - __bfloat162float(h0)));
        L.y = bf16bits(__float2bfloat16_rn(y1 - __bfloat162float(h1)));
        L.z = bf16bits(__float2bfloat16_rn(y2 - __bfloat162float(h2)));
        L.w = bf16bits(__float2bfloat16_rn(y3 - __bfloat162float(h3)));
        reinterpret_cast<ushort4*>(h)[i] = H;
        reinterpret_cast<ushort4*>(l)[i] = L;
    }
}

// ---------------- launch ----------------
extern "C" void kernel_launch(void* const* d_in, const int* in_sizes, int n_in,
                              void* d_out, int out_size) {
    const float* x   = (const float*)d_in[0];
    const int*   ei  = (const int*)d_in[1];
    const float* W1  = (const float*)d_in[2];
    const float* as1 = (const float*)d_in[3];
    const float* ad1 = (const float*)d_in[4];
    const float* b1  = (const float*)d_in[5];
    const float* ga1 = (const float*)d_in[6];
    const float* be1 = (const float*)d_in[7];
    const float* W2  = (const float*)d_in[8];
    const float* as2 = (const float*)d_in[9];
    const float* ad2 = (const float*)d_in[10];
    const float* b2  = (const float*)d_in[11];
    const float* ga2 = (const float*)d_in[12];
    const float* be2 = (const float*)d_in[13];
    const float* W3  = (const float*)d_in[14];
    const float* as3 = (const float*)d_in[15];
    const float* ad3 = (const float*)d_in[16];
    const float* b3  = (const float*)d_in[17];
    float* out = (float*)d_out;

    float *bufA, *bufB;
    unsigned short *ah, *al, *wh, *wl;
    cudaGetSymbolAddress((void**)&bufA, g_bufA);
    cudaGetSymbolAddress((void**)&bufB, g_bufB);
    cudaGetSymbolAddress((void**)&ah, g_ah);
    cudaGetSymbolAddress((void**)&al, g_al);
    cudaGetSymbolAddress((void**)&wh, g_wh);
    cudaGetSymbolAddress((void**)&wl, g_wl);

    cudaFuncSetAttribute(gemm_cp, cudaFuncAttributeMaxDynamicSharedMemorySize,
                         SMEM_GEMM_BYTES);

    static cudaStream_t s2 = nullptr;
    static cudaEvent_t evFork = nullptr, evCsr = nullptr, evW = nullptr, evW1 = nullptr;
    if (!s2) {
        cudaStreamCreateWithFlags(&s2, cudaStreamNonBlocking);
        cudaEventCreateWithFlags(&evFork, cudaEventDisableTiming);
        cudaEventCreateWithFlags(&evCsr, cudaEventDisableTiming);
        cudaEventCreateWithFlags(&evW, cudaEventDisableTiming);
        cudaEventCreateWithFlags(&evW1, cudaEventDisableTiming);
    }

    const dim3 gemmGrid(4, (NN + TM - 1) / TM);   // 4 x 105 = 420 CTAs, single wave

    // ---- fork: splitw1 first (needed by gemm1), then CSR build + W2/W3 splits ----
    cudaEventRecord(evFork, 0);
    cudaStreamWaitEvent(s2, evFork, 0);
    splitw_kernel<<<(IN_DIM * HC + 255) / 256, 256, 0, s2>>>(W1, wh, wl, IN_DIM, HC, HC, WOFF1);
    cudaEventRecord(evW1, s2);
    hist_kernel<<<(ETOT + 255) / 256, 256, 0, s2>>>(ei);
    scan_kernel<<<1, 1024, 0, s2>>>();
    scatter_kernel<<<(ETOT + 255) / 256, 256, 0, s2>>>(ei);
    cudaEventRecord(evCsr, s2);
    splitw_kernel<<<(HC * HC + 255) / 256, 256, 0, s2>>>(W2, wh, wl, HC, HC, HC, WOFF2);
    splitw_kernel<<<(HC * 512 + 255) / 256, 256, 0, s2>>>(W3, wh, wl, HC, OUTD, 512, WOFF3);
    cudaEventRecord(evW, s2);

    // ---- main stream: layer 1 (splita runs concurrent with splitw1) ----
    {
        int n4 = NN * IN_DIM / 4;
        splita_kernel<<<(n4 + 255) / 256, 256>>>(x, ah, al, n4);
    }
    cudaStreamWaitEvent(0, evW1, 0);
    gemm_cp<<<gemmGrid, 192, SMEM_GEMM_BYTES>>>(
        NN, HC, HC, IN_DIM, ah, al, wh + WOFF1, wl + WOFF1, bufA,
        as1, ad1, HEADS, HIDC);

    cudaStreamWaitEvent(0, evCsr, 0);
    gather_fused<HEADS, HIDC><<<NN, 128>>>(bufA, b1, bufB, 1);
    bn_stats_kernel<<<(NN + 255) / 256, 512>>>(bufB, ga1, be1);
    bn_apply_split_kernel<<<(NN * HC / 4 + 255) / 256, 256>>>(bufB, ah, al, 0);

    // ---- layer 2 ----
    cudaStreamWaitEvent(0, evW, 0);
    gemm_cp<<<gemmGrid, 192, SMEM_GEMM_BYTES>>>(
        NN, HC, HC, HC, ah, al, wh + WOFF2, wl + WOFF2, bufA,
        as2, ad2, HEADS, HIDC);
    gather_fused<HEADS, HIDC><<<NN, 128>>>(bufA, b2, bufB, 1);
    bn_stats_kernel<<<(NN + 255) / 256, 512>>>(bufB, ga2, be2);
    bn_apply_split_kernel<<<(NN * HC / 4 + 255) / 256, 256>>>(bufB, ah, al, 1);

    // ---- layer 3 (W3 padded to 512 cols; H=1) ----
    gemm_cp<<<gemmGrid, 192, SMEM_GEMM_BYTES>>>(
        NN, OUTD, 512, HC, ah, al, wh + WOFF3, wl + WOFF3, bufA,
        as3, ad3, 1, OUTD);
    gather_fused<1, OUTD><<<NN, 128>>>(bufA, b3, out, 0);
}